// round 1
// baseline (speedup 1.0000x reference)
#include <cuda_runtime.h>
#include <math.h>

#define B_  8
#define S_  1024
#define D_  1024
#define H_  16
#define A_  4
#define DK_ 128

// ---------------- scratch (static device allocations; no cudaMalloc) --------
__device__ float g_xmean[B_ * D_];
__device__ int   g_idx [B_ * A_];
__device__ float g_gate[B_ * A_];
__device__ float g_Q[(size_t)B_ * A_ * S_ * DK_];
__device__ float g_K[(size_t)B_ * A_ * S_ * DK_];
__device__ float g_V[(size_t)B_ * A_ * S_ * DK_];
__device__ float g_cat[(size_t)B_ * S_ * A_ * DK_];

// ---------------- 1) mean over sequence -------------------------------------
__global__ void mean_kernel(const float* __restrict__ x) {
    int b = blockIdx.y;
    int d = blockIdx.x * 256 + threadIdx.x;
    const float* xp = x + (size_t)b * S_ * D_ + d;
    float s = 0.f;
    #pragma unroll 4
    for (int t = 0; t < S_; ++t) s += xp[(size_t)t * D_];
    g_xmean[b * D_ + d] = s * (1.0f / (float)S_);
}

// ---------------- 2) router: logits, softmax, top-k, re-softmax gates -------
__global__ void router_kernel(const float* __restrict__ Wr,
                              const float* __restrict__ br) {
    int b = blockIdx.x;
    __shared__ float red[128][H_];
    int tid = threadIdx.x;  // 128 threads
    float acc[H_];
    #pragma unroll
    for (int h = 0; h < H_; ++h) acc[h] = 0.f;
    for (int d = tid; d < D_; d += 128) {
        float xv = g_xmean[b * D_ + d];
        #pragma unroll
        for (int h = 0; h < H_; ++h) acc[h] += xv * Wr[d * H_ + h];
    }
    #pragma unroll
    for (int h = 0; h < H_; ++h) red[tid][h] = acc[h];
    __syncthreads();
    if (tid == 0) {
        float logit[H_];
        for (int h = 0; h < H_; ++h) {
            float s = 0.f;
            for (int t = 0; t < 128; ++t) s += red[t][h];
            logit[h] = s + br[h];
        }
        // softmax over heads
        float mx = logit[0];
        for (int h = 1; h < H_; ++h) mx = fmaxf(mx, logit[h]);
        float dist[H_], sum = 0.f;
        for (int h = 0; h < H_; ++h) { dist[h] = expf(logit[h] - mx); sum += dist[h]; }
        for (int h = 0; h < H_; ++h) dist[h] /= sum;
        // top-4 (descending, first index wins ties) — matches jax.lax.top_k
        bool used[H_];
        for (int h = 0; h < H_; ++h) used[h] = false;
        int   idxs[A_];
        float vals[A_];
        for (int a = 0; a < A_; ++a) {
            int best = -1; float bv = -1.f;
            for (int h = 0; h < H_; ++h)
                if (!used[h] && dist[h] > bv) { bv = dist[h]; best = h; }
            used[best] = true; idxs[a] = best; vals[a] = bv;
        }
        // sparse scatter + softmax over all 16 heads: 12 zeros contribute exp(0)=1
        float denom = (float)(H_ - A_);
        float ev[A_];
        for (int a = 0; a < A_; ++a) { ev[a] = expf(vals[a]); denom += ev[a]; }
        for (int a = 0; a < A_; ++a) {
            g_idx [b * A_ + a] = idxs[a];
            g_gate[b * A_ + a] = ev[a] / denom;
        }
    }
}

// ---------------- generic 128x128xK fp32 GEMM tile --------------------------
// A: row-major, pre-offset to tile row 0; B: row-major K x N, pre-offset to col 0;
// C: pre-offset to tile origin. All dims multiples of tile sizes (no bounds checks).
__device__ __forceinline__ void gemm_tile_128(
    const float* __restrict__ A, int lda,
    const float* __restrict__ Bm, int ldb,
    const float* __restrict__ bias,
    float* __restrict__ C, int ldc, int K)
{
    __shared__ float As[16][132];   // A tile stored transposed, padded
    __shared__ float Bs[16][128];
    int tid = threadIdx.x;          // 256 threads
    int tx = tid & 15, ty = tid >> 4;

    float acc[8][8];
    #pragma unroll
    for (int i = 0; i < 8; ++i)
        #pragma unroll
        for (int j = 0; j < 8; ++j) acc[i][j] = 0.f;

    for (int k0 = 0; k0 < K; k0 += 16) {
        #pragma unroll
        for (int l = 0; l < 8; ++l) {           // 128x16 A tile
            int e = tid + l * 256;
            int r = e >> 4, c = e & 15;
            As[c][r] = A[(size_t)r * lda + k0 + c];
        }
        #pragma unroll
        for (int l = 0; l < 8; ++l) {           // 16x128 B tile
            int e = tid + l * 256;
            int r = e >> 7, c = e & 127;
            Bs[r][c] = Bm[(size_t)(k0 + r) * ldb + c];
        }
        __syncthreads();
        #pragma unroll
        for (int kk = 0; kk < 16; ++kk) {
            float a[8], bb[8];
            *(float4*)(a)      = *(const float4*)&As[kk][ty * 8];
            *(float4*)(a + 4)  = *(const float4*)&As[kk][ty * 8 + 4];
            *(float4*)(bb)     = *(const float4*)&Bs[kk][tx * 8];
            *(float4*)(bb + 4) = *(const float4*)&Bs[kk][tx * 8 + 4];
            #pragma unroll
            for (int i = 0; i < 8; ++i)
                #pragma unroll
                for (int j = 0; j < 8; ++j)
                    acc[i][j] = fmaf(a[i], bb[j], acc[i][j]);
        }
        __syncthreads();
    }
    #pragma unroll
    for (int i = 0; i < 8; ++i) {
        int r = ty * 8 + i;
        float4 o0, o1;
        o0.x = acc[i][0] + bias[tx * 8 + 0];
        o0.y = acc[i][1] + bias[tx * 8 + 1];
        o0.z = acc[i][2] + bias[tx * 8 + 2];
        o0.w = acc[i][3] + bias[tx * 8 + 3];
        o1.x = acc[i][4] + bias[tx * 8 + 4];
        o1.y = acc[i][5] + bias[tx * 8 + 5];
        o1.z = acc[i][6] + bias[tx * 8 + 6];
        o1.w = acc[i][7] + bias[tx * 8 + 7];
        *(float4*)&C[(size_t)r * ldc + tx * 8]     = o0;
        *(float4*)&C[(size_t)r * ldc + tx * 8 + 4] = o1;
    }
}

// ---------------- 3) gathered QKV projections --------------------------------
// grid: (S/128, 3, B*A), block 256
__global__ void qkv_kernel(const float* __restrict__ x,
                           const float* __restrict__ Wq, const float* __restrict__ bq,
                           const float* __restrict__ Wk, const float* __restrict__ bk,
                           const float* __restrict__ Wv, const float* __restrict__ bv) {
    int z = blockIdx.z;
    int b = z >> 2;
    int h = g_idx[z];
    const float *W, *bias; float* out;
    if (blockIdx.y == 0)      { W = Wq; bias = bq; out = g_Q; }
    else if (blockIdx.y == 1) { W = Wk; bias = bk; out = g_K; }
    else                      { W = Wv; bias = bv; out = g_V; }
    const float* A  = x + (size_t)b * S_ * D_ + (size_t)blockIdx.x * 128 * D_;
    const float* Bm = W + (size_t)h * D_ * DK_;
    float*       C  = out + (size_t)z * S_ * DK_ + (size_t)blockIdx.x * 128 * DK_;
    gemm_tile_128(A, D_, Bm, DK_, bias + h * DK_, C, DK_, D_);
}

// ---------------- 4) flash attention + gate + concat -------------------------
// grid: (S/64, B*A), block 256 (8 warps x 8 rows), dynamic smem
#define FLASH_SMEM_FLOATS (64 * 128 + 128 * 66 + 64 * 128)
__global__ void flash_kernel() {
    extern __shared__ float sm[];
    float* Qs = sm;                    // [64][128], pre-scaled
    float* Kt = sm + 64 * 128;         // [128][66]: Kt[k*66 + j] = K[key j][k]
    float* Vs = Kt + 128 * 66;         // [64][128]

    int z = blockIdx.y;
    int b = z >> 2, a = z & 3;
    const float* Q = g_Q + (size_t)z * S_ * DK_;
    const float* K = g_K + (size_t)z * S_ * DK_;
    const float* V = g_V + (size_t)z * S_ * DK_;
    int tid = threadIdx.x, lane = tid & 31, w = tid >> 5;
    int qrow0 = blockIdx.x * 64;
    const float sc = 0.08838834764831845f;   // 1/sqrt(128)

    for (int e = tid; e < 64 * 128; e += 256) {
        int r = e >> 7, c = e & 127;
        Qs[e] = Q[(size_t)(qrow0 + r) * DK_ + c] * sc;
    }

    float acc[8][4];
    float m[8], l[8];
    #pragma unroll
    for (int r = 0; r < 8; ++r) {
        m[r] = -3.0e38f; l[r] = 0.f;
        #pragma unroll
        for (int u = 0; u < 4; ++u) acc[r][u] = 0.f;
    }

    for (int kt = 0; kt < S_ / 64; ++kt) {
        __syncthreads();   // previous PV phase must finish before overwrite
        for (int e = tid; e < 64 * 128; e += 256) {
            int k = e & 127, j = e >> 7;
            Kt[k * 66 + j] = K[(size_t)(kt * 64 + j) * DK_ + k];
            Vs[e]          = V[(size_t)(kt * 64 + j) * DK_ + k];
        }
        __syncthreads();

        // scores: lane owns keys 2*lane and 2*lane+1
        float s2[8][2];
        #pragma unroll
        for (int r = 0; r < 8; ++r) { s2[r][0] = 0.f; s2[r][1] = 0.f; }
        #pragma unroll 4
        for (int k = 0; k < 128; ++k) {
            float2 kk2 = *(const float2*)&Kt[k * 66 + 2 * lane];
            #pragma unroll
            for (int r = 0; r < 8; ++r) {
                float q = Qs[(w * 8 + r) * 128 + k];
                s2[r][0] = fmaf(q, kk2.x, s2[r][0]);
                s2[r][1] = fmaf(q, kk2.y, s2[r][1]);
            }
        }

        // online softmax per row
        #pragma unroll
        for (int r = 0; r < 8; ++r) {
            float mt = fmaxf(s2[r][0], s2[r][1]);
            #pragma unroll
            for (int off = 16; off; off >>= 1)
                mt = fmaxf(mt, __shfl_xor_sync(0xffffffffu, mt, off));
            float mnew = fmaxf(m[r], mt);
            float p0 = __expf(s2[r][0] - mnew);
            float p1 = __expf(s2[r][1] - mnew);
            float ls = p0 + p1;
            #pragma unroll
            for (int off = 16; off; off >>= 1)
                ls += __shfl_xor_sync(0xffffffffu, ls, off);
            float alpha = __expf(m[r] - mnew);
            m[r] = mnew;
            l[r] = l[r] * alpha + ls;
            #pragma unroll
            for (int u = 0; u < 4; ++u) acc[r][u] *= alpha;
            s2[r][0] = p0; s2[r][1] = p1;
        }

        // PV: acc[r][u] += p[r][jj] * V[jj][lane + 32u]
        #pragma unroll 4
        for (int jj = 0; jj < 64; ++jj) {
            float v0 = Vs[jj * 128 + lane];
            float v1 = Vs[jj * 128 + lane + 32];
            float v2 = Vs[jj * 128 + lane + 64];
            float v3 = Vs[jj * 128 + lane + 96];
            #pragma unroll
            for (int r = 0; r < 8; ++r) {
                float pj = __shfl_sync(0xffffffffu, s2[r][jj & 1], jj >> 1);
                acc[r][0] = fmaf(pj, v0, acc[r][0]);
                acc[r][1] = fmaf(pj, v1, acc[r][1]);
                acc[r][2] = fmaf(pj, v2, acc[r][2]);
                acc[r][3] = fmaf(pj, v3, acc[r][3]);
            }
        }
    }

    // epilogue: normalize, gate, write into concat layout [B][S][A*DK]
    float g = g_gate[z];
    #pragma unroll
    for (int r = 0; r < 8; ++r) {
        int row = qrow0 + w * 8 + r;
        float invl = g / l[r];
        float* o = g_cat + ((size_t)b * S_ + row) * (A_ * DK_) + a * DK_;
        o[lane]      = acc[r][0] * invl;
        o[lane + 32] = acc[r][1] * invl;
        o[lane + 64] = acc[r][2] * invl;
        o[lane + 96] = acc[r][3] * invl;
    }
}

// ---------------- 5) output projection ---------------------------------------
// grid: (B*S/128, D/128), block 256
__global__ void outproj_kernel(const float* __restrict__ Wo,
                               const float* __restrict__ bo,
                               float* __restrict__ out) {
    const float* A  = g_cat + (size_t)blockIdx.x * 128 * (A_ * DK_);
    const float* Bm = Wo + blockIdx.y * 128;
    float*       C  = out + (size_t)blockIdx.x * 128 * D_ + blockIdx.y * 128;
    gemm_tile_128(A, A_ * DK_, Bm, D_, bo + blockIdx.y * 128, C, D_, A_ * DK_);
}

// ---------------- launch ------------------------------------------------------
extern "C" void kernel_launch(void* const* d_in, const int* in_sizes, int n_in,
                              void* d_out, int out_size) {
    const float* x  = (const float*)d_in[0];
    const float* Wq = (const float*)d_in[1];
    const float* bq = (const float*)d_in[2];
    const float* Wk = (const float*)d_in[3];
    const float* bk = (const float*)d_in[4];
    const float* Wv = (const float*)d_in[5];
    const float* bv = (const float*)d_in[6];
    const float* Wr = (const float*)d_in[7];
    const float* br = (const float*)d_in[8];
    const float* Wo = (const float*)d_in[9];
    const float* bo = (const float*)d_in[10];
    float* out = (float*)d_out;

    cudaFuncSetAttribute(flash_kernel,
                         cudaFuncAttributeMaxDynamicSharedMemorySize,
                         FLASH_SMEM_FLOATS * (int)sizeof(float));

    mean_kernel  <<<dim3(D_ / 256, B_), 256>>>(x);
    router_kernel<<<B_, 128>>>(Wr, br);
    qkv_kernel   <<<dim3(S_ / 128, 3, B_ * A_), 256>>>(x, Wq, bq, Wk, bk, Wv, bv);
    flash_kernel <<<dim3(S_ / 64, B_ * A_), 256,
                    FLASH_SMEM_FLOATS * (int)sizeof(float)>>>();
    outproj_kernel<<<dim3((B_ * S_) / 128, D_ / 128), 256>>>(Wo, bo, out);
}

// round 3
// speedup vs baseline: 1.1794x; 1.1794x over previous
#include <cuda_runtime.h>
#include <math.h>
#include <stdint.h>

#define B_  8
#define S_  1024
#define D_  1024
#define H_  16
#define A_  4
#define DK_ 128

// ---------------- scratch (static device allocations; no cudaMalloc) --------
__device__ float g_xmean[B_ * D_];
__device__ int   g_idx [B_ * A_];
__device__ float g_gate[B_ * A_];
__device__ float g_Q[(size_t)B_ * A_ * S_ * DK_];
__device__ float g_K[(size_t)B_ * A_ * S_ * DK_];
__device__ float g_V[(size_t)B_ * A_ * S_ * DK_];
__device__ float g_cat[(size_t)B_ * S_ * A_ * DK_];
// transposed weights: [h][n][k] (col-major B for mma row.col)
__device__ float g_WqT[(size_t)H_ * DK_ * D_];
__device__ float g_WkT[(size_t)H_ * DK_ * D_];
__device__ float g_WvT[(size_t)H_ * DK_ * D_];
__device__ float g_WoT[(size_t)D_ * (A_ * DK_)];   // [1024 n][512 k]

// ---------------- helpers -----------------------------------------------------
static __device__ __forceinline__ uint32_t tf32r(float x) {
    uint32_t u;
    asm("cvt.rna.tf32.f32 %0, %1;" : "=r"(u) : "f"(x));
    return u;
}
// split x into hi/lo tf32 pair (bit patterns as float)
static __device__ __forceinline__ float2 tf32split(float x) {
    uint32_t hu = tf32r(x);
    float h = __uint_as_float(hu);
    uint32_t lu = tf32r(x - h);
    return make_float2(h, __uint_as_float(lu));
}
static __device__ __forceinline__ void mma1688(float* c, const uint32_t* a,
                                               const uint32_t* b) {
    asm volatile(
        "mma.sync.aligned.m16n8k8.row.col.f32.tf32.tf32.f32 "
        "{%0,%1,%2,%3}, {%4,%5,%6,%7}, {%8,%9}, {%0,%1,%2,%3};"
        : "+f"(c[0]), "+f"(c[1]), "+f"(c[2]), "+f"(c[3])
        : "r"(a[0]), "r"(a[1]), "r"(a[2]), "r"(a[3]), "r"(b[0]), "r"(b[1]));
}

// ---------------- 1) mean over sequence -------------------------------------
__global__ void mean_kernel(const float* __restrict__ x) {
    int b = blockIdx.y;
    int d = blockIdx.x * 256 + threadIdx.x;
    const float* xp = x + (size_t)b * S_ * D_ + d;
    float s = 0.f;
    #pragma unroll 4
    for (int t = 0; t < S_; ++t) s += xp[(size_t)t * D_];
    g_xmean[b * D_ + d] = s * (1.0f / (float)S_);
}

// ---------------- 2) router ---------------------------------------------------
__global__ void router_kernel(const float* __restrict__ Wr,
                              const float* __restrict__ br) {
    int b = blockIdx.x;
    __shared__ float red[128][H_];
    int tid = threadIdx.x;
    float acc[H_];
    #pragma unroll
    for (int h = 0; h < H_; ++h) acc[h] = 0.f;
    for (int d = tid; d < D_; d += 128) {
        float xv = g_xmean[b * D_ + d];
        #pragma unroll
        for (int h = 0; h < H_; ++h) acc[h] += xv * Wr[d * H_ + h];
    }
    #pragma unroll
    for (int h = 0; h < H_; ++h) red[tid][h] = acc[h];
    __syncthreads();
    if (tid == 0) {
        float logit[H_];
        for (int h = 0; h < H_; ++h) {
            float s = 0.f;
            for (int t = 0; t < 128; ++t) s += red[t][h];
            logit[h] = s + br[h];
        }
        float mx = logit[0];
        for (int h = 1; h < H_; ++h) mx = fmaxf(mx, logit[h]);
        float dist[H_], sum = 0.f;
        for (int h = 0; h < H_; ++h) { dist[h] = expf(logit[h] - mx); sum += dist[h]; }
        for (int h = 0; h < H_; ++h) dist[h] /= sum;
        bool used[H_];
        for (int h = 0; h < H_; ++h) used[h] = false;
        int idxs[A_]; float vals[A_];
        for (int a = 0; a < A_; ++a) {
            int best = -1; float bv = -1.f;
            for (int h = 0; h < H_; ++h)
                if (!used[h] && dist[h] > bv) { bv = dist[h]; best = h; }
            used[best] = true; idxs[a] = best; vals[a] = bv;
        }
        float denom = (float)(H_ - A_);
        float ev[A_];
        for (int a = 0; a < A_; ++a) { ev[a] = expf(vals[a]); denom += ev[a]; }
        for (int a = 0; a < A_; ++a) {
            g_idx [b * A_ + a] = idxs[a];
            g_gate[b * A_ + a] = ev[a] / denom;
        }
    }
}

// ---------------- weight transposes ------------------------------------------
__global__ void transpose_heads(const float* __restrict__ Wq,
                                const float* __restrict__ Wk,
                                const float* __restrict__ Wv) {
    __shared__ float t[32][33];
    int zb = blockIdx.z;
    int mat = zb >> 4, h = zb & 15;
    const float* W = (mat == 0) ? Wq : (mat == 1) ? Wk : Wv;
    float*       O = (mat == 0) ? g_WqT : (mat == 1) ? g_WkT : g_WvT;
    int k0 = blockIdx.x * 32, n0 = blockIdx.y * 32;
    int tx = threadIdx.x, ty = threadIdx.y;
    const float* Wh = W + (size_t)h * D_ * DK_;
    float*       Oh = O + (size_t)h * DK_ * D_;
    #pragma unroll
    for (int i = 0; i < 4; ++i)
        t[ty + 8 * i][tx] = Wh[(size_t)(k0 + ty + 8 * i) * DK_ + n0 + tx];
    __syncthreads();
    #pragma unroll
    for (int i = 0; i < 4; ++i)
        Oh[(size_t)(n0 + ty + 8 * i) * D_ + k0 + tx] = t[tx][ty + 8 * i];
}

__global__ void transpose_wo(const float* __restrict__ Wo) {
    __shared__ float t[32][33];
    int k0 = blockIdx.x * 32, n0 = blockIdx.y * 32;
    int tx = threadIdx.x, ty = threadIdx.y;
    #pragma unroll
    for (int i = 0; i < 4; ++i)
        t[ty + 8 * i][tx] = Wo[(size_t)(k0 + ty + 8 * i) * D_ + n0 + tx];
    __syncthreads();
    #pragma unroll
    for (int i = 0; i < 4; ++i)
        g_WoT[(size_t)(n0 + ty + 8 * i) * (A_ * DK_) + k0 + tx] = t[tx][ty + 8 * i];
}

// ============ split-tf32 mma GEMM: C[128,128] = A[128,K] @ Bt[128,K]^T =======
// A row-major [128,K]; Bt row-major [128,K] (i.e. B col-major). 256 threads.
// Each fp32 k-element is split into (hi,lo) tf32 pair -> SMEM holds 2x k slots.
#define KCH 16                       // global k per chunk
#define PITCH 36                     // smem floats per row (32 slots + 4 pad)

static __device__ __forceinline__ void gemm128_mma(
    const float* __restrict__ A, int lda,
    const float* __restrict__ Bt, int ldb,
    const float* __restrict__ bias,
    float* __restrict__ C, int ldc, int K)
{
    __shared__ float As[128 * PITCH];
    __shared__ float Bs[128 * PITCH];

    const int tid  = threadIdx.x;
    const int lane = tid & 31;
    const int wid  = tid >> 5;
    const int wm   = wid & 3;          // warp row: 32 rows each
    const int wn   = wid >> 2;         // warp col: 64 cols each
    const int g    = lane >> 2;        // group 0..7
    const int tig  = lane & 3;         // 0..3

    // global load mapping: 2 float4 per thread per matrix per chunk
    const int e0 = tid * 2;
    const int row0 = e0 >> 2,        qg0 = e0 & 3;
    const int row1 = (e0 + 1) >> 2,  qg1 = (e0 + 1) & 3;

    float acc[2][8][4];
    #pragma unroll
    for (int mi = 0; mi < 2; ++mi)
        #pragma unroll
        for (int ni = 0; ni < 8; ++ni)
            #pragma unroll
            for (int r = 0; r < 4; ++r) acc[mi][ni][r] = 0.f;

    const int KIT = K / KCH;

    float4 ra0, ra1, rb0, rb1;
    ra0 = *(const float4*)(A  + (size_t)row0 * lda + qg0 * 4);
    ra1 = *(const float4*)(A  + (size_t)row1 * lda + qg1 * 4);
    rb0 = *(const float4*)(Bt + (size_t)row0 * ldb + qg0 * 4);
    rb1 = *(const float4*)(Bt + (size_t)row1 * ldb + qg1 * 4);

    for (int it = 0; it < KIT; ++it) {
        // store current chunk (hi/lo interleaved)
        {
            float2 h0 = tf32split(ra0.x), h1 = tf32split(ra0.y),
                   h2 = tf32split(ra0.z), h3 = tf32split(ra0.w);
            *(float4*)&As[row0 * PITCH + 8 * qg0]     = make_float4(h0.x, h0.y, h1.x, h1.y);
            *(float4*)&As[row0 * PITCH + 8 * qg0 + 4] = make_float4(h2.x, h2.y, h3.x, h3.y);
            h0 = tf32split(ra1.x); h1 = tf32split(ra1.y);
            h2 = tf32split(ra1.z); h3 = tf32split(ra1.w);
            *(float4*)&As[row1 * PITCH + 8 * qg1]     = make_float4(h0.x, h0.y, h1.x, h1.y);
            *(float4*)&As[row1 * PITCH + 8 * qg1 + 4] = make_float4(h2.x, h2.y, h3.x, h3.y);
            h0 = tf32split(rb0.x); h1 = tf32split(rb0.y);
            h2 = tf32split(rb0.z); h3 = tf32split(rb0.w);
            *(float4*)&Bs[row0 * PITCH + 8 * qg0]     = make_float4(h0.x, h0.y, h1.x, h1.y);
            *(float4*)&Bs[row0 * PITCH + 8 * qg0 + 4] = make_float4(h2.x, h2.y, h3.x, h3.y);
            h0 = tf32split(rb1.x); h1 = tf32split(rb1.y);
            h2 = tf32split(rb1.z); h3 = tf32split(rb1.w);
            *(float4*)&Bs[row1 * PITCH + 8 * qg1]     = make_float4(h0.x, h0.y, h1.x, h1.y);
            *(float4*)&Bs[row1 * PITCH + 8 * qg1 + 4] = make_float4(h2.x, h2.y, h3.x, h3.y);
        }
        __syncthreads();

        if (it + 1 < KIT) {
            const float* An = A  + (size_t)(it + 1) * KCH;
            const float* Bn = Bt + (size_t)(it + 1) * KCH;
            ra0 = *(const float4*)(An + (size_t)row0 * lda + qg0 * 4);
            ra1 = *(const float4*)(An + (size_t)row1 * lda + qg1 * 4);
            rb0 = *(const float4*)(Bn + (size_t)row0 * ldb + qg0 * 4);
            rb1 = *(const float4*)(Bn + (size_t)row1 * ldb + qg1 * 4);
        }

        // mma over 32 tf32 slots = 4 k-steps of 8
        #pragma unroll
        for (int ks = 0; ks < 4; ++ks) {
            uint32_t a[2][4];
            #pragma unroll
            for (int mi = 0; mi < 2; ++mi) {
                const float* ap = &As[(wm * 32 + mi * 16 + g) * PITCH + ks * 8 + tig];
                a[mi][0] = __float_as_uint(ap[0]);
                a[mi][1] = __float_as_uint(ap[8 * PITCH]);
                a[mi][2] = __float_as_uint(ap[4]);
                a[mi][3] = __float_as_uint(ap[8 * PITCH + 4]);
            }
            #pragma unroll
            for (int ni = 0; ni < 8; ++ni) {
                const float* bp = &Bs[(wn * 64 + ni * 8 + g) * PITCH + ks * 8 + tig];
                uint32_t b[2];
                b[0] = __float_as_uint(bp[0]);
                b[1] = __float_as_uint(bp[4]);
                mma1688(acc[0][ni], a[0], b);
                mma1688(acc[1][ni], a[1], b);
            }
        }
        __syncthreads();
    }

    // epilogue with bias
    #pragma unroll
    for (int mi = 0; mi < 2; ++mi) {
        int r0 = wm * 32 + mi * 16 + g;
        #pragma unroll
        for (int ni = 0; ni < 8; ++ni) {
            int c = wn * 64 + ni * 8 + 2 * tig;
            float b0 = __ldg(bias + c), b1 = __ldg(bias + c + 1);
            *(float2*)&C[(size_t)r0 * ldc + c] =
                make_float2(acc[mi][ni][0] + b0, acc[mi][ni][1] + b1);
            *(float2*)&C[(size_t)(r0 + 8) * ldc + c] =
                make_float2(acc[mi][ni][2] + b0, acc[mi][ni][3] + b1);
        }
    }
}

// ---------------- 3) gathered QKV projections (tensor mma) -------------------
__global__ void __launch_bounds__(256) qkv_tc(const float* __restrict__ x,
                                              const float* __restrict__ bq,
                                              const float* __restrict__ bk,
                                              const float* __restrict__ bv) {
    int z = blockIdx.z;
    int b = z >> 2;
    int h = g_idx[z];
    const float* Bt; const float* bias; float* out;
    if (blockIdx.y == 0)      { Bt = g_WqT; bias = bq; out = g_Q; }
    else if (blockIdx.y == 1) { Bt = g_WkT; bias = bk; out = g_K; }
    else                      { Bt = g_WvT; bias = bv; out = g_V; }
    Bt   += (size_t)h * DK_ * D_;
    bias += h * DK_;
    const float* Atile = x + (size_t)b * S_ * D_ + (size_t)blockIdx.x * 128 * D_;
    float* C = out + (size_t)z * S_ * DK_ + (size_t)blockIdx.x * 128 * DK_;
    gemm128_mma(Atile, D_, Bt, D_, bias, C, DK_, D_);
}

// ---------------- 4) flash attention + gate + concat -------------------------
#define FLASH_SMEM_FLOATS (64 * 128 + 128 * 66 + 64 * 128)
__global__ void flash_kernel() {
    extern __shared__ float sm[];
    float* Qs = sm;
    float* Kt = sm + 64 * 128;
    float* Vs = Kt + 128 * 66;

    int z = blockIdx.y;
    int b = z >> 2, a = z & 3;
    const float* Q = g_Q + (size_t)z * S_ * DK_;
    const float* K = g_K + (size_t)z * S_ * DK_;
    const float* V = g_V + (size_t)z * S_ * DK_;
    int tid = threadIdx.x, lane = tid & 31, w = tid >> 5;
    int qrow0 = blockIdx.x * 64;
    const float sc = 0.08838834764831845f;

    for (int e = tid; e < 64 * 128; e += 256) {
        int r = e >> 7, c = e & 127;
        Qs[e] = Q[(size_t)(qrow0 + r) * DK_ + c] * sc;
    }

    float acc[8][4];
    float m[8], l[8];
    #pragma unroll
    for (int r = 0; r < 8; ++r) {
        m[r] = -3.0e38f; l[r] = 0.f;
        #pragma unroll
        for (int u = 0; u < 4; ++u) acc[r][u] = 0.f;
    }

    for (int kt = 0; kt < S_ / 64; ++kt) {
        __syncthreads();
        for (int e = tid; e < 64 * 128; e += 256) {
            int k = e & 127, j = e >> 7;
            Kt[k * 66 + j] = K[(size_t)(kt * 64 + j) * DK_ + k];
            Vs[e]          = V[(size_t)(kt * 64 + j) * DK_ + k];
        }
        __syncthreads();

        float s2[8][2];
        #pragma unroll
        for (int r = 0; r < 8; ++r) { s2[r][0] = 0.f; s2[r][1] = 0.f; }
        #pragma unroll 4
        for (int k = 0; k < 128; ++k) {
            float2 kk2 = *(const float2*)&Kt[k * 66 + 2 * lane];
            #pragma unroll
            for (int r = 0; r < 8; ++r) {
                float q = Qs[(w * 8 + r) * 128 + k];
                s2[r][0] = fmaf(q, kk2.x, s2[r][0]);
                s2[r][1] = fmaf(q, kk2.y, s2[r][1]);
            }
        }

        #pragma unroll
        for (int r = 0; r < 8; ++r) {
            float mt = fmaxf(s2[r][0], s2[r][1]);
            #pragma unroll
            for (int off = 16; off; off >>= 1)
                mt = fmaxf(mt, __shfl_xor_sync(0xffffffffu, mt, off));
            float mnew = fmaxf(m[r], mt);
            float p0 = __expf(s2[r][0] - mnew);
            float p1 = __expf(s2[r][1] - mnew);
            float ls = p0 + p1;
            #pragma unroll
            for (int off = 16; off; off >>= 1)
                ls += __shfl_xor_sync(0xffffffffu, ls, off);
            float alpha = __expf(m[r] - mnew);
            m[r] = mnew;
            l[r] = l[r] * alpha + ls;
            #pragma unroll
            for (int u = 0; u < 4; ++u) acc[r][u] *= alpha;
            s2[r][0] = p0; s2[r][1] = p1;
        }

        #pragma unroll 4
        for (int jj = 0; jj < 64; ++jj) {
            float v0 = Vs[jj * 128 + lane];
            float v1 = Vs[jj * 128 + lane + 32];
            float v2 = Vs[jj * 128 + lane + 64];
            float v3 = Vs[jj * 128 + lane + 96];
            #pragma unroll
            for (int r = 0; r < 8; ++r) {
                float pj = __shfl_sync(0xffffffffu, s2[r][jj & 1], jj >> 1);
                acc[r][0] = fmaf(pj, v0, acc[r][0]);
                acc[r][1] = fmaf(pj, v1, acc[r][1]);
                acc[r][2] = fmaf(pj, v2, acc[r][2]);
                acc[r][3] = fmaf(pj, v3, acc[r][3]);
            }
        }
    }

    float g = g_gate[z];
    #pragma unroll
    for (int r = 0; r < 8; ++r) {
        int row = qrow0 + w * 8 + r;
        float invl = g / l[r];
        float* o = g_cat + ((size_t)b * S_ + row) * (A_ * DK_) + a * DK_;
        o[lane]      = acc[r][0] * invl;
        o[lane + 32] = acc[r][1] * invl;
        o[lane + 64] = acc[r][2] * invl;
        o[lane + 96] = acc[r][3] * invl;
    }
}

// ---------------- 5) output projection (tensor mma) ---------------------------
__global__ void __launch_bounds__(256) outproj_tc(const float* __restrict__ bo,
                                                  float* __restrict__ out) {
    const float* Atile = g_cat + (size_t)blockIdx.x * 128 * (A_ * DK_);
    const float* Bt = g_WoT + (size_t)blockIdx.y * 128 * (A_ * DK_);
    const float* bias = bo + blockIdx.y * 128;
    float* C = out + (size_t)blockIdx.x * 128 * D_ + blockIdx.y * 128;
    gemm128_mma(Atile, A_ * DK_, Bt, A_ * DK_, bias, C, D_, A_ * DK_);
}

// ---------------- launch ------------------------------------------------------
extern "C" void kernel_launch(void* const* d_in, const int* in_sizes, int n_in,
                              void* d_out, int out_size) {
    const float* x  = (const float*)d_in[0];
    const float* Wq = (const float*)d_in[1];
    const float* bq = (const float*)d_in[2];
    const float* Wk = (const float*)d_in[3];
    const float* bk = (const float*)d_in[4];
    const float* Wv = (const float*)d_in[5];
    const float* bv = (const float*)d_in[6];
    const float* Wr = (const float*)d_in[7];
    const float* br = (const float*)d_in[8];
    const float* Wo = (const float*)d_in[9];
    const float* bo = (const float*)d_in[10];
    float* out = (float*)d_out;

    cudaFuncSetAttribute(flash_kernel,
                         cudaFuncAttributeMaxDynamicSharedMemorySize,
                         FLASH_SMEM_FLOATS * (int)sizeof(float));

    mean_kernel     <<<dim3(D_ / 256, B_), 256>>>(x);
    router_kernel   <<<B_, 128>>>(Wr, br);
    transpose_heads <<<dim3(D_ / 32, DK_ / 32, 3 * H_), dim3(32, 8)>>>(Wq, Wk, Wv);
    transpose_wo    <<<dim3((A_ * DK_) / 32, D_ / 32), dim3(32, 8)>>>(Wo);
    qkv_tc          <<<dim3(S_ / 128, 3, B_ * A_), 256>>>(x, bq, bk, bv);
    flash_kernel    <<<dim3(S_ / 64, B_ * A_), 256,
                       FLASH_SMEM_FLOATS * (int)sizeof(float)>>>();
    outproj_tc      <<<dim3((B_ * S_) / 128, D_ / 128), 256>>>(bo, out);
}

// round 4
// speedup vs baseline: 2.0406x; 1.7301x over previous
#include <cuda_runtime.h>
#include <math.h>
#include <stdint.h>

#define B_  8
#define S_  1024
#define D_  1024
#define H_  16
#define A_  4
#define DK_ 128

// ---------------- scratch (static device allocations; no cudaMalloc) --------
__device__ float g_xmean[B_ * D_];
__device__ int   g_idx [B_ * A_];
__device__ float g_gate[B_ * A_];
__device__ float g_Q[(size_t)B_ * A_ * S_ * DK_];
__device__ float g_K[(size_t)B_ * A_ * S_ * DK_];
__device__ float g_V[(size_t)B_ * A_ * S_ * DK_];
__device__ float g_cat[(size_t)B_ * S_ * A_ * DK_];
// transposed weights: [h][n][k] (col-major B for mma row.col)
__device__ float g_WqT[(size_t)H_ * DK_ * D_];
__device__ float g_WkT[(size_t)H_ * DK_ * D_];
__device__ float g_WvT[(size_t)H_ * DK_ * D_];
__device__ float g_WoT[(size_t)D_ * (A_ * DK_)];   // [1024 n][512 k]

// ---------------- helpers -----------------------------------------------------
static __device__ __forceinline__ uint32_t tf32r(float x) {
    uint32_t u;
    asm("cvt.rna.tf32.f32 %0, %1;" : "=r"(u) : "f"(x));
    return u;
}
static __device__ __forceinline__ float tf32f(float x) {
    return __uint_as_float(tf32r(x));
}
static __device__ __forceinline__ void mma1688(float* c, const uint32_t* a,
                                               const uint32_t* b) {
    asm volatile(
        "mma.sync.aligned.m16n8k8.row.col.f32.tf32.tf32.f32 "
        "{%0,%1,%2,%3}, {%4,%5,%6,%7}, {%8,%9}, {%0,%1,%2,%3};"
        : "+f"(c[0]), "+f"(c[1]), "+f"(c[2]), "+f"(c[3])
        : "r"(a[0]), "r"(a[1]), "r"(a[2]), "r"(a[3]), "r"(b[0]), "r"(b[1]));
}

// ---------------- 1) mean over sequence -------------------------------------
__global__ void mean_kernel(const float* __restrict__ x) {
    int b = blockIdx.y;
    int d = blockIdx.x * 256 + threadIdx.x;
    const float* xp = x + (size_t)b * S_ * D_ + d;
    float s = 0.f;
    #pragma unroll 4
    for (int t = 0; t < S_; ++t) s += xp[(size_t)t * D_];
    g_xmean[b * D_ + d] = s * (1.0f / (float)S_);
}

// ---------------- 2) router ---------------------------------------------------
__global__ void router_kernel(const float* __restrict__ Wr,
                              const float* __restrict__ br) {
    int b = blockIdx.x;
    __shared__ float red[128][H_];
    int tid = threadIdx.x;
    float acc[H_];
    #pragma unroll
    for (int h = 0; h < H_; ++h) acc[h] = 0.f;
    for (int d = tid; d < D_; d += 128) {
        float xv = g_xmean[b * D_ + d];
        #pragma unroll
        for (int h = 0; h < H_; ++h) acc[h] += xv * Wr[d * H_ + h];
    }
    #pragma unroll
    for (int h = 0; h < H_; ++h) red[tid][h] = acc[h];
    __syncthreads();
    if (tid == 0) {
        float logit[H_];
        for (int h = 0; h < H_; ++h) {
            float s = 0.f;
            for (int t = 0; t < 128; ++t) s += red[t][h];
            logit[h] = s + br[h];
        }
        float mx = logit[0];
        for (int h = 1; h < H_; ++h) mx = fmaxf(mx, logit[h]);
        float dist[H_], sum = 0.f;
        for (int h = 0; h < H_; ++h) { dist[h] = expf(logit[h] - mx); sum += dist[h]; }
        for (int h = 0; h < H_; ++h) dist[h] /= sum;
        bool used[H_];
        for (int h = 0; h < H_; ++h) used[h] = false;
        int idxs[A_]; float vals[A_];
        for (int a = 0; a < A_; ++a) {
            int best = -1; float bv = -1.f;
            for (int h = 0; h < H_; ++h)
                if (!used[h] && dist[h] > bv) { bv = dist[h]; best = h; }
            used[best] = true; idxs[a] = best; vals[a] = bv;
        }
        float denom = (float)(H_ - A_);
        float ev[A_];
        for (int a = 0; a < A_; ++a) { ev[a] = expf(vals[a]); denom += ev[a]; }
        for (int a = 0; a < A_; ++a) {
            g_idx [b * A_ + a] = idxs[a];
            g_gate[b * A_ + a] = ev[a] / denom;
        }
    }
}

// ---------------- weight transposes ------------------------------------------
__global__ void transpose_heads(const float* __restrict__ Wq,
                                const float* __restrict__ Wk,
                                const float* __restrict__ Wv) {
    __shared__ float t[32][33];
    int zb = blockIdx.z;
    int mat = zb >> 4, h = zb & 15;
    const float* W = (mat == 0) ? Wq : (mat == 1) ? Wk : Wv;
    float*       O = (mat == 0) ? g_WqT : (mat == 1) ? g_WkT : g_WvT;
    int k0 = blockIdx.x * 32, n0 = blockIdx.y * 32;
    int tx = threadIdx.x, ty = threadIdx.y;
    const float* Wh = W + (size_t)h * D_ * DK_;
    float*       Oh = O + (size_t)h * DK_ * D_;
    #pragma unroll
    for (int i = 0; i < 4; ++i)
        t[ty + 8 * i][tx] = Wh[(size_t)(k0 + ty + 8 * i) * DK_ + n0 + tx];
    __syncthreads();
    #pragma unroll
    for (int i = 0; i < 4; ++i)
        Oh[(size_t)(n0 + ty + 8 * i) * D_ + k0 + tx] = t[tx][ty + 8 * i];
}

__global__ void transpose_wo(const float* __restrict__ Wo) {
    __shared__ float t[32][33];
    int k0 = blockIdx.x * 32, n0 = blockIdx.y * 32;
    int tx = threadIdx.x, ty = threadIdx.y;
    #pragma unroll
    for (int i = 0; i < 4; ++i)
        t[ty + 8 * i][tx] = Wo[(size_t)(k0 + ty + 8 * i) * D_ + n0 + tx];
    __syncthreads();
    #pragma unroll
    for (int i = 0; i < 4; ++i)
        g_WoT[(size_t)(n0 + ty + 8 * i) * (A_ * DK_) + k0 + tx] = t[tx][ty + 8 * i];
}

// ======= single-slot tf32 mma GEMM: C[128,128] = A[128,K] @ Bt[128,K]^T ======
#define KCH 32
#define PITCH 36

static __device__ __forceinline__ void gemm128_mma(
    const float* __restrict__ A, int lda,
    const float* __restrict__ Bt, int ldb,
    const float* __restrict__ bias,
    float* __restrict__ C, int ldc, int K)
{
    __shared__ float As[128 * PITCH];
    __shared__ float Bs[128 * PITCH];

    const int tid  = threadIdx.x;
    const int lane = tid & 31;
    const int wid  = tid >> 5;
    const int wm   = wid & 3;          // warp row: 32 rows each
    const int wn   = wid >> 2;         // warp col: 64 cols each
    const int g    = lane >> 2;
    const int tig  = lane & 3;

    const int row = tid >> 1;          // smem row this thread fills
    const int qb  = (tid & 1) * 4;     // float4 index base (0 or 4) of 8/row

    float acc[2][8][4];
    #pragma unroll
    for (int mi = 0; mi < 2; ++mi)
        #pragma unroll
        for (int ni = 0; ni < 8; ++ni)
            #pragma unroll
            for (int r = 0; r < 4; ++r) acc[mi][ni][r] = 0.f;

    const int KIT = K / KCH;
    const float* Ap = A  + (size_t)row * lda + qb * 4;
    const float* Bp = Bt + (size_t)row * ldb + qb * 4;

    float4 ra[4], rb[4];
    #pragma unroll
    for (int i = 0; i < 4; ++i) {
        ra[i] = *(const float4*)(Ap + i * 4);
        rb[i] = *(const float4*)(Bp + i * 4);
    }

    for (int it = 0; it < KIT; ++it) {
        #pragma unroll
        for (int i = 0; i < 4; ++i) {
            float4 v = ra[i];
            v.x = tf32f(v.x); v.y = tf32f(v.y); v.z = tf32f(v.z); v.w = tf32f(v.w);
            *(float4*)&As[row * PITCH + (qb + i) * 4] = v;
            float4 w = rb[i];
            w.x = tf32f(w.x); w.y = tf32f(w.y); w.z = tf32f(w.z); w.w = tf32f(w.w);
            *(float4*)&Bs[row * PITCH + (qb + i) * 4] = w;
        }
        __syncthreads();

        if (it + 1 < KIT) {
            const float* An = Ap + (size_t)(it + 1) * KCH;
            const float* Bn = Bp + (size_t)(it + 1) * KCH;
            #pragma unroll
            for (int i = 0; i < 4; ++i) {
                ra[i] = *(const float4*)(An + i * 4);
                rb[i] = *(const float4*)(Bn + i * 4);
            }
        }

        #pragma unroll
        for (int ks = 0; ks < 4; ++ks) {
            uint32_t a[2][4];
            #pragma unroll
            for (int mi = 0; mi < 2; ++mi) {
                const float* ap = &As[(wm * 32 + mi * 16 + g) * PITCH + ks * 8 + tig];
                a[mi][0] = __float_as_uint(ap[0]);
                a[mi][1] = __float_as_uint(ap[8 * PITCH]);
                a[mi][2] = __float_as_uint(ap[4]);
                a[mi][3] = __float_as_uint(ap[8 * PITCH + 4]);
            }
            #pragma unroll
            for (int ni = 0; ni < 8; ++ni) {
                const float* bp = &Bs[(wn * 64 + ni * 8 + g) * PITCH + ks * 8 + tig];
                uint32_t b[2];
                b[0] = __float_as_uint(bp[0]);
                b[1] = __float_as_uint(bp[4]);
                mma1688(acc[0][ni], a[0], b);
                mma1688(acc[1][ni], a[1], b);
            }
        }
        __syncthreads();
    }

    #pragma unroll
    for (int mi = 0; mi < 2; ++mi) {
        int r0 = wm * 32 + mi * 16 + g;
        #pragma unroll
        for (int ni = 0; ni < 8; ++ni) {
            int c = wn * 64 + ni * 8 + 2 * tig;
            float b0 = __ldg(bias + c), b1 = __ldg(bias + c + 1);
            *(float2*)&C[(size_t)r0 * ldc + c] =
                make_float2(acc[mi][ni][0] + b0, acc[mi][ni][1] + b1);
            *(float2*)&C[(size_t)(r0 + 8) * ldc + c] =
                make_float2(acc[mi][ni][2] + b0, acc[mi][ni][3] + b1);
        }
    }
}

// ---------------- 3) gathered QKV projections (tensor mma) -------------------
__global__ void __launch_bounds__(256) qkv_tc(const float* __restrict__ x,
                                              const float* __restrict__ bq,
                                              const float* __restrict__ bk,
                                              const float* __restrict__ bv) {
    int z = blockIdx.z;
    int b = z >> 2;
    int h = g_idx[z];
    const float* Bt; const float* bias; float* out;
    if (blockIdx.y == 0)      { Bt = g_WqT; bias = bq; out = g_Q; }
    else if (blockIdx.y == 1) { Bt = g_WkT; bias = bk; out = g_K; }
    else                      { Bt = g_WvT; bias = bv; out = g_V; }
    Bt   += (size_t)h * DK_ * D_;
    bias += h * DK_;
    const float* Atile = x + (size_t)b * S_ * D_ + (size_t)blockIdx.x * 128 * D_;
    float* C = out + (size_t)z * S_ * DK_ + (size_t)blockIdx.x * 128 * DK_;
    gemm128_mma(Atile, D_, Bt, D_, bias, C, DK_, D_);
}

// ---------------- 4) tensor-core flash attention + gate + concat -------------
// grid (S/128, B*A), block 256 (8 warps, m16 each covering 128 Q rows)
// smem: Qs[128][132], Kt[64][132], Vt[128][68] (V transposed), Ps[128][68]
#define FL_SMEM_FLOATS (128 * 132 + 64 * 132 + 128 * 68 + 128 * 68)

__global__ void __launch_bounds__(256, 1) flash_tc() {
    extern __shared__ float fs[];
    float* Qs = fs;
    float* Kt = Qs + 128 * 132;
    float* Vt = Kt + 64 * 132;
    float* Ps = Vt + 128 * 68;

    const int z = blockIdx.y, b = z >> 2, a = z & 3;
    const float* Qg = g_Q + (size_t)z * S_ * DK_;
    const float* Kg = g_K + (size_t)z * S_ * DK_;
    const float* Vg = g_V + (size_t)z * S_ * DK_;
    const int tid = threadIdx.x, lane = tid & 31, w = tid >> 5;
    const int g = lane >> 2, tig = lane & 3;
    const int m0 = w * 16;
    const int qrow0 = blockIdx.x * 128;
    const float sc = 0.08838834764831845f;   // 1/sqrt(128)

    // load Q (pre-scaled, tf32-rounded)
    for (int e = tid; e < 128 * 128; e += 256) {
        int r = e >> 7, c = e & 127;
        Qs[r * 132 + c] = tf32f(Qg[(size_t)(qrow0 + r) * DK_ + c] * sc);
    }

    float o[16][4];
    #pragma unroll
    for (int ni = 0; ni < 16; ++ni)
        #pragma unroll
        for (int r = 0; r < 4; ++r) o[ni][r] = 0.f;
    float mr0 = -1e30f, mr1 = -1e30f, l0 = 0.f, l1 = 0.f;

    for (int kt = 0; kt < S_ / 64; ++kt) {
        __syncthreads();
        for (int e = tid; e < 64 * 128; e += 256) {
            int key = e >> 7, dk = e & 127;
            Kt[key * 132 + dk] = tf32f(Kg[(size_t)(kt * 64 + key) * DK_ + dk]);
            Vt[dk * 68 + key]  = tf32f(Vg[(size_t)(kt * 64 + key) * DK_ + dk]);
        }
        __syncthreads();

        // ---- S = Q K^T (16 k-steps over dk, 8 n-tiles over 64 keys) ----
        float sacc[8][4];
        #pragma unroll
        for (int ni = 0; ni < 8; ++ni)
            #pragma unroll
            for (int r = 0; r < 4; ++r) sacc[ni][r] = 0.f;

        #pragma unroll
        for (int ks = 0; ks < 16; ++ks) {
            uint32_t aq[4];
            const float* qp = &Qs[(m0 + g) * 132 + ks * 8 + tig];
            aq[0] = __float_as_uint(qp[0]);
            aq[1] = __float_as_uint(qp[8 * 132]);
            aq[2] = __float_as_uint(qp[4]);
            aq[3] = __float_as_uint(qp[8 * 132 + 4]);
            #pragma unroll
            for (int ni = 0; ni < 8; ++ni) {
                const float* kp = &Kt[(ni * 8 + g) * 132 + ks * 8 + tig];
                uint32_t bb[2] = { __float_as_uint(kp[0]), __float_as_uint(kp[4]) };
                mma1688(sacc[ni], aq, bb);
            }
        }

        // ---- online softmax on fragment (rows g and g+8 of warp m-tile) ----
        float mt0 = -1e30f, mt1 = -1e30f;
        #pragma unroll
        for (int ni = 0; ni < 8; ++ni) {
            mt0 = fmaxf(mt0, fmaxf(sacc[ni][0], sacc[ni][1]));
            mt1 = fmaxf(mt1, fmaxf(sacc[ni][2], sacc[ni][3]));
        }
        mt0 = fmaxf(mt0, __shfl_xor_sync(0xffffffffu, mt0, 1));
        mt0 = fmaxf(mt0, __shfl_xor_sync(0xffffffffu, mt0, 2));
        mt1 = fmaxf(mt1, __shfl_xor_sync(0xffffffffu, mt1, 1));
        mt1 = fmaxf(mt1, __shfl_xor_sync(0xffffffffu, mt1, 2));

        float mn0 = fmaxf(mr0, mt0), mn1 = fmaxf(mr1, mt1);
        float al0 = __expf(mr0 - mn0), al1 = __expf(mr1 - mn1);
        float ls0 = 0.f, ls1 = 0.f;
        #pragma unroll
        for (int ni = 0; ni < 8; ++ni) {
            sacc[ni][0] = __expf(sacc[ni][0] - mn0);
            sacc[ni][1] = __expf(sacc[ni][1] - mn0);
            sacc[ni][2] = __expf(sacc[ni][2] - mn1);
            sacc[ni][3] = __expf(sacc[ni][3] - mn1);
            ls0 += sacc[ni][0] + sacc[ni][1];
            ls1 += sacc[ni][2] + sacc[ni][3];
        }
        ls0 += __shfl_xor_sync(0xffffffffu, ls0, 1);
        ls0 += __shfl_xor_sync(0xffffffffu, ls0, 2);
        ls1 += __shfl_xor_sync(0xffffffffu, ls1, 1);
        ls1 += __shfl_xor_sync(0xffffffffu, ls1, 2);

        l0 = l0 * al0 + ls0;  mr0 = mn0;
        l1 = l1 * al1 + ls1;  mr1 = mn1;

        #pragma unroll
        for (int ni = 0; ni < 16; ++ni) {
            o[ni][0] *= al0; o[ni][1] *= al0;
            o[ni][2] *= al1; o[ni][3] *= al1;
        }

        // ---- write P (warp-private rows) ----
        #pragma unroll
        for (int ni = 0; ni < 8; ++ni) {
            *(float2*)&Ps[(m0 + g) * 68 + ni * 8 + 2 * tig] =
                make_float2(tf32f(sacc[ni][0]), tf32f(sacc[ni][1]));
            *(float2*)&Ps[(m0 + g + 8) * 68 + ni * 8 + 2 * tig] =
                make_float2(tf32f(sacc[ni][2]), tf32f(sacc[ni][3]));
        }
        __syncwarp();

        // ---- O += P V (8 k-steps over keys, 16 n-tiles over dk) ----
        #pragma unroll
        for (int ks = 0; ks < 8; ++ks) {
            uint32_t ap[4];
            const float* pp = &Ps[(m0 + g) * 68 + ks * 8 + tig];
            ap[0] = __float_as_uint(pp[0]);
            ap[1] = __float_as_uint(pp[8 * 68]);
            ap[2] = __float_as_uint(pp[4]);
            ap[3] = __float_as_uint(pp[8 * 68 + 4]);
            #pragma unroll
            for (int ni = 0; ni < 16; ++ni) {
                const float* vp = &Vt[(ni * 8 + g) * 68 + ks * 8 + tig];
                uint32_t bb[2] = { __float_as_uint(vp[0]), __float_as_uint(vp[4]) };
                mma1688(o[ni], ap, bb);
            }
        }
    }

    // ---- epilogue: normalize, gate, concat layout ----
    float gate = g_gate[z];
    float inv0 = gate / l0, inv1 = gate / l1;
    int r0 = qrow0 + m0 + g, r1 = r0 + 8;
    float* ob0 = g_cat + ((size_t)b * S_ + r0) * (A_ * DK_) + a * DK_;
    float* ob1 = g_cat + ((size_t)b * S_ + r1) * (A_ * DK_) + a * DK_;
    #pragma unroll
    for (int ni = 0; ni < 16; ++ni) {
        int c = ni * 8 + 2 * tig;
        *(float2*)&ob0[c] = make_float2(o[ni][0] * inv0, o[ni][1] * inv0);
        *(float2*)&ob1[c] = make_float2(o[ni][2] * inv1, o[ni][3] * inv1);
    }
}

// ---------------- 5) output projection (tensor mma) ---------------------------
__global__ void __launch_bounds__(256) outproj_tc(const float* __restrict__ bo,
                                                  float* __restrict__ out) {
    const float* Atile = g_cat + (size_t)blockIdx.x * 128 * (A_ * DK_);
    const float* Bt = g_WoT + (size_t)blockIdx.y * 128 * (A_ * DK_);
    const float* bias = bo + blockIdx.y * 128;
    float* C = out + (size_t)blockIdx.x * 128 * D_ + blockIdx.y * 128;
    gemm128_mma(Atile, A_ * DK_, Bt, A_ * DK_, bias, C, D_, A_ * DK_);
}

// ---------------- launch ------------------------------------------------------
extern "C" void kernel_launch(void* const* d_in, const int* in_sizes, int n_in,
                              void* d_out, int out_size) {
    const float* x  = (const float*)d_in[0];
    const float* Wq = (const float*)d_in[1];
    const float* bq = (const float*)d_in[2];
    const float* Wk = (const float*)d_in[3];
    const float* bk = (const float*)d_in[4];
    const float* Wv = (const float*)d_in[5];
    const float* bv = (const float*)d_in[6];
    const float* Wr = (const float*)d_in[7];
    const float* br = (const float*)d_in[8];
    const float* Wo = (const float*)d_in[9];
    const float* bo = (const float*)d_in[10];
    float* out = (float*)d_out;

    cudaFuncSetAttribute(flash_tc,
                         cudaFuncAttributeMaxDynamicSharedMemorySize,
                         FL_SMEM_FLOATS * (int)sizeof(float));

    mean_kernel     <<<dim3(D_ / 256, B_), 256>>>(x);
    router_kernel   <<<B_, 128>>>(Wr, br);
    transpose_heads <<<dim3(D_ / 32, DK_ / 32, 3 * H_), dim3(32, 8)>>>(Wq, Wk, Wv);
    transpose_wo    <<<dim3((A_ * DK_) / 32, D_ / 32), dim3(32, 8)>>>(Wo);
    qkv_tc          <<<dim3(S_ / 128, 3, B_ * A_), 256>>>(x, bq, bk, bv);
    flash_tc        <<<dim3(S_ / 128, B_ * A_), 256,
                       FL_SMEM_FLOATS * (int)sizeof(float)>>>();
    outproj_tc      <<<dim3((B_ * S_) / 128, D_ / 128), 256>>>(bo, out);
}

// round 5
// speedup vs baseline: 2.0525x; 1.0058x over previous
#include <cuda_runtime.h>
#include <math.h>
#include <stdint.h>

#define B_  8
#define S_  1024
#define D_  1024
#define H_  16
#define A_  4
#define DK_ 128

// ---------------- scratch (static device allocations) ------------------------
__device__ float g_xmean[B_ * D_];
__device__ int   g_idx [B_ * A_];
__device__ float g_gate[B_ * A_];
__device__ float g_xt [(size_t)B_ * S_ * D_];            // tf32-rounded x
__device__ float g_Q  [(size_t)B_ * A_ * S_ * DK_];      // pre-scaled, tf32
__device__ float g_K  [(size_t)B_ * A_ * S_ * DK_];      // tf32
__device__ float g_Vt [(size_t)B_ * A_ * DK_ * S_];      // transposed [z][dk][s], tf32
__device__ float g_cat[(size_t)B_ * S_ * A_ * DK_];      // tf32
__device__ float g_WqT[(size_t)H_ * DK_ * D_];           // [h][n][k], tf32
__device__ float g_WkT[(size_t)H_ * DK_ * D_];
__device__ float g_WvT[(size_t)H_ * DK_ * D_];
__device__ float g_WoT[(size_t)D_ * (A_ * DK_)];

// ---------------- helpers -----------------------------------------------------
static __device__ __forceinline__ float tf32f(float x) {
    uint32_t u;
    asm("cvt.rna.tf32.f32 %0, %1;" : "=r"(u) : "f"(x));
    return __uint_as_float(u);
}
static __device__ __forceinline__ void mma1688(float* c, const uint32_t* a,
                                               const uint32_t* b) {
    asm volatile(
        "mma.sync.aligned.m16n8k8.row.col.f32.tf32.tf32.f32 "
        "{%0,%1,%2,%3}, {%4,%5,%6,%7}, {%8,%9}, {%0,%1,%2,%3};"
        : "+f"(c[0]), "+f"(c[1]), "+f"(c[2]), "+f"(c[3])
        : "r"(a[0]), "r"(a[1]), "r"(a[2]), "r"(a[3]), "r"(b[0]), "r"(b[1]));
}
static __device__ __forceinline__ uint32_t smem_u32(const void* p) {
    uint32_t a;
    asm("{ .reg .u64 t; cvta.to.shared.u64 t, %1; cvt.u32.u64 %0, t; }"
        : "=r"(a) : "l"(p));
    return a;
}
#define CP16(dst, src) \
    asm volatile("cp.async.cg.shared.global [%0], [%1], 16;" :: "r"(dst), "l"(src))
#define CP_COMMIT() asm volatile("cp.async.commit_group;" ::: "memory")
#define CP_WAIT(n)  asm volatile("cp.async.wait_group %0;" :: "n"(n) : "memory")

// ---------------- 1) mean over sequence + tf32 copy of x ----------------------
__global__ void mean_kernel(const float* __restrict__ x) {
    int b = blockIdx.y;
    int d = blockIdx.x * 256 + threadIdx.x;
    const float* xp = x + (size_t)b * S_ * D_ + d;
    float s = 0.f;
    #pragma unroll 4
    for (int t = 0; t < S_; ++t) s += xp[(size_t)t * D_];
    g_xmean[b * D_ + d] = s * (1.0f / (float)S_);
}
__global__ void copy_x_tf32(const float* __restrict__ x) {
    size_t i = ((size_t)blockIdx.x * 256 + threadIdx.x) * 4;
    float4 v = *(const float4*)(x + i);
    v.x = tf32f(v.x); v.y = tf32f(v.y); v.z = tf32f(v.z); v.w = tf32f(v.w);
    *(float4*)(g_xt + i) = v;
}

// ---------------- 2) router ---------------------------------------------------
__global__ void router_kernel(const float* __restrict__ Wr,
                              const float* __restrict__ br) {
    int b = blockIdx.x;
    __shared__ float red[128][H_];
    int tid = threadIdx.x;
    float acc[H_];
    #pragma unroll
    for (int h = 0; h < H_; ++h) acc[h] = 0.f;
    for (int d = tid; d < D_; d += 128) {
        float xv = g_xmean[b * D_ + d];
        #pragma unroll
        for (int h = 0; h < H_; ++h) acc[h] += xv * Wr[d * H_ + h];
    }
    #pragma unroll
    for (int h = 0; h < H_; ++h) red[tid][h] = acc[h];
    __syncthreads();
    if (tid == 0) {
        float logit[H_];
        for (int h = 0; h < H_; ++h) {
            float s = 0.f;
            for (int t = 0; t < 128; ++t) s += red[t][h];
            logit[h] = s + br[h];
        }
        float mx = logit[0];
        for (int h = 1; h < H_; ++h) mx = fmaxf(mx, logit[h]);
        float dist[H_], sum = 0.f;
        for (int h = 0; h < H_; ++h) { dist[h] = expf(logit[h] - mx); sum += dist[h]; }
        for (int h = 0; h < H_; ++h) dist[h] /= sum;
        bool used[H_];
        for (int h = 0; h < H_; ++h) used[h] = false;
        int idxs[A_]; float vals[A_];
        for (int a = 0; a < A_; ++a) {
            int best = -1; float bv = -1.f;
            for (int h = 0; h < H_; ++h)
                if (!used[h] && dist[h] > bv) { bv = dist[h]; best = h; }
            used[best] = true; idxs[a] = best; vals[a] = bv;
        }
        float denom = (float)(H_ - A_);
        float ev[A_];
        for (int a = 0; a < A_; ++a) { ev[a] = expf(vals[a]); denom += ev[a]; }
        for (int a = 0; a < A_; ++a) {
            g_idx [b * A_ + a] = idxs[a];
            g_gate[b * A_ + a] = ev[a] / denom;
        }
    }
}

// ---------------- weight transposes (emit tf32-rounded) -----------------------
__global__ void transpose_heads(const float* __restrict__ Wq,
                                const float* __restrict__ Wk,
                                const float* __restrict__ Wv) {
    __shared__ float t[32][33];
    int zb = blockIdx.z;
    int mat = zb >> 4, h = zb & 15;
    const float* W = (mat == 0) ? Wq : (mat == 1) ? Wk : Wv;
    float*       O = (mat == 0) ? g_WqT : (mat == 1) ? g_WkT : g_WvT;
    int k0 = blockIdx.x * 32, n0 = blockIdx.y * 32;
    int tx = threadIdx.x, ty = threadIdx.y;
    const float* Wh = W + (size_t)h * D_ * DK_;
    float*       Oh = O + (size_t)h * DK_ * D_;
    #pragma unroll
    for (int i = 0; i < 4; ++i)
        t[ty + 8 * i][tx] = Wh[(size_t)(k0 + ty + 8 * i) * DK_ + n0 + tx];
    __syncthreads();
    #pragma unroll
    for (int i = 0; i < 4; ++i)
        Oh[(size_t)(n0 + ty + 8 * i) * D_ + k0 + tx] = tf32f(t[tx][ty + 8 * i]);
}

__global__ void transpose_wo(const float* __restrict__ Wo) {
    __shared__ float t[32][33];
    int k0 = blockIdx.x * 32, n0 = blockIdx.y * 32;
    int tx = threadIdx.x, ty = threadIdx.y;
    #pragma unroll
    for (int i = 0; i < 4; ++i)
        t[ty + 8 * i][tx] = Wo[(size_t)(k0 + ty + 8 * i) * D_ + n0 + tx];
    __syncthreads();
    #pragma unroll
    for (int i = 0; i < 4; ++i)
        g_WoT[(size_t)(n0 + ty + 8 * i) * (A_ * DK_) + k0 + tx] = tf32f(t[tx][ty + 8 * i]);
}

// ======= cp.async-pipelined tf32 GEMM: C[128,128] = A[128,K] @ Bt[128,K]^T ====
// Operands pre-rounded tf32. 2-stage double buffer, 256 threads.
// EPI: 0 plain (+bias), 1 Q ((acc+bias)*sc, tf32), 2 V transposed (+bias, tf32),
//      3 K (+bias, tf32)
#define PITCH 36
#define GEMM_SMEM_BYTES (4 * 128 * PITCH * 4)   // 73728

template<int EPI>
static __device__ __forceinline__ void gemm128_pipe(
    const float* __restrict__ A, int lda,
    const float* __restrict__ Bt, int ldb,
    const float* __restrict__ bias,
    float* __restrict__ C, int ldc, int K, float sc)
{
    extern __shared__ float sh[];
    float* As[2] = { sh,            sh + 128 * PITCH };
    float* Bs[2] = { sh + 2 * 128 * PITCH, sh + 3 * 128 * PITCH };

    const int tid  = threadIdx.x;
    const int lane = tid & 31;
    const int wid  = tid >> 5;
    const int wm   = wid & 3;
    const int wn   = wid >> 2;
    const int g    = lane >> 2;
    const int tig  = lane & 3;

    const int row  = tid >> 1;           // 0..127
    const int half = (tid & 1) * 16;     // float offset within 32-float chunk

    const float* Ap = A  + (size_t)row * lda + half;
    const float* Bp = Bt + (size_t)row * ldb + half;
    uint32_t sA[2], sB[2];
    sA[0] = smem_u32(&As[0][row * PITCH + half]);
    sA[1] = smem_u32(&As[1][row * PITCH + half]);
    sB[0] = smem_u32(&Bs[0][row * PITCH + half]);
    sB[1] = smem_u32(&Bs[1][row * PITCH + half]);

    const int KIT = K >> 5;

    // prologue: stage 0
    #pragma unroll
    for (int j = 0; j < 4; ++j) {
        CP16(sA[0] + j * 16, Ap + j * 4);
        CP16(sB[0] + j * 16, Bp + j * 4);
    }
    CP_COMMIT();

    float acc[2][8][4];
    #pragma unroll
    for (int mi = 0; mi < 2; ++mi)
        #pragma unroll
        for (int ni = 0; ni < 8; ++ni)
            #pragma unroll
            for (int r = 0; r < 4; ++r) acc[mi][ni][r] = 0.f;

    for (int it = 0; it < KIT; ++it) {
        if (it + 1 < KIT) {
            const float* An = Ap + (size_t)(it + 1) * 32;
            const float* Bn = Bp + (size_t)(it + 1) * 32;
            int nb = (it + 1) & 1;
            #pragma unroll
            for (int j = 0; j < 4; ++j) {
                CP16(sA[nb] + j * 16, An + j * 4);
                CP16(sB[nb] + j * 16, Bn + j * 4);
            }
            CP_COMMIT();
            CP_WAIT(1);
        } else {
            CP_WAIT(0);
        }
        __syncthreads();

        const float* Ab = As[it & 1];
        const float* Bb = Bs[it & 1];
        #pragma unroll
        for (int ks = 0; ks < 4; ++ks) {
            uint32_t a[2][4];
            #pragma unroll
            for (int mi = 0; mi < 2; ++mi) {
                const float* ap = &Ab[(wm * 32 + mi * 16 + g) * PITCH + ks * 8 + tig];
                a[mi][0] = __float_as_uint(ap[0]);
                a[mi][1] = __float_as_uint(ap[8 * PITCH]);
                a[mi][2] = __float_as_uint(ap[4]);
                a[mi][3] = __float_as_uint(ap[8 * PITCH + 4]);
            }
            #pragma unroll
            for (int ni = 0; ni < 8; ++ni) {
                const float* bp = &Bb[(wn * 64 + ni * 8 + g) * PITCH + ks * 8 + tig];
                uint32_t b[2];
                b[0] = __float_as_uint(bp[0]);
                b[1] = __float_as_uint(bp[4]);
                mma1688(acc[0][ni], a[0], b);
                mma1688(acc[1][ni], a[1], b);
            }
        }
        __syncthreads();
    }

    #pragma unroll
    for (int mi = 0; mi < 2; ++mi) {
        int r0 = wm * 32 + mi * 16 + g;
        #pragma unroll
        for (int ni = 0; ni < 8; ++ni) {
            int c = wn * 64 + ni * 8 + 2 * tig;
            float b0 = __ldg(bias + c), b1 = __ldg(bias + c + 1);
            float v0 = acc[mi][ni][0] + b0, v1 = acc[mi][ni][1] + b1;
            float v2 = acc[mi][ni][2] + b0, v3 = acc[mi][ni][3] + b1;
            if (EPI == 0) {
                *(float2*)&C[(size_t)r0 * ldc + c]       = make_float2(v0, v1);
                *(float2*)&C[(size_t)(r0 + 8) * ldc + c] = make_float2(v2, v3);
            } else if (EPI == 1) {
                *(float2*)&C[(size_t)r0 * ldc + c] =
                    make_float2(tf32f(v0 * sc), tf32f(v1 * sc));
                *(float2*)&C[(size_t)(r0 + 8) * ldc + c] =
                    make_float2(tf32f(v2 * sc), tf32f(v3 * sc));
            } else if (EPI == 2) {
                // transposed: C + c*ldc + r
                C[(size_t)c * ldc + r0]           = tf32f(v0);
                C[(size_t)(c + 1) * ldc + r0]     = tf32f(v1);
                C[(size_t)c * ldc + r0 + 8]       = tf32f(v2);
                C[(size_t)(c + 1) * ldc + r0 + 8] = tf32f(v3);
            } else {
                *(float2*)&C[(size_t)r0 * ldc + c] =
                    make_float2(tf32f(v0), tf32f(v1));
                *(float2*)&C[(size_t)(r0 + 8) * ldc + c] =
                    make_float2(tf32f(v2), tf32f(v3));
            }
        }
    }
}

// ---------------- 3) gathered QKV projections ---------------------------------
__global__ void __launch_bounds__(256, 2) qkv_tc(const float* __restrict__ bq,
                                                 const float* __restrict__ bk,
                                                 const float* __restrict__ bv) {
    int z = blockIdx.z;
    int b = z >> 2;
    int h = g_idx[z];
    const float* Atile = g_xt + (size_t)b * S_ * D_ + (size_t)blockIdx.x * 128 * D_;
    const float sc = 0.08838834764831845f;
    if (blockIdx.y == 0) {
        float* C = g_Q + (size_t)z * S_ * DK_ + (size_t)blockIdx.x * 128 * DK_;
        gemm128_pipe<1>(Atile, D_, g_WqT + (size_t)h * DK_ * D_, D_,
                        bq + h * DK_, C, DK_, D_, sc);
    } else if (blockIdx.y == 1) {
        float* C = g_K + (size_t)z * S_ * DK_ + (size_t)blockIdx.x * 128 * DK_;
        gemm128_pipe<3>(Atile, D_, g_WkT + (size_t)h * DK_ * D_, D_,
                        bk + h * DK_, C, DK_, D_, 1.f);
    } else {
        float* C = g_Vt + (size_t)z * DK_ * S_ + blockIdx.x * 128;  // [dk][s] base
        gemm128_pipe<2>(Atile, D_, g_WvT + (size_t)h * DK_ * D_, D_,
                        bv + h * DK_, C, S_, D_, 1.f);
    }
}

// ---------------- 4) tensor-core flash attention (cp.async pipelined) --------
// grid (S/128, B*A), block 256 (8 warps). smem floats:
//   Qs [128*132] @0, K0 [64*132] @16896, K1 @25344, Vt [128*68] @33792, Ps @42496
#define FL_Q   0
#define FL_K0  16896
#define FL_K1  25344
#define FL_V   33792
#define FL_P   42496
#define FL_SMEM_FLOATS 51200

__global__ void __launch_bounds__(256, 1) flash_tc() {
    extern __shared__ float fs[];
    const int z = blockIdx.y, b = z >> 2, a = z & 3;
    const float* Qg = g_Q + (size_t)z * S_ * DK_;
    const float* Kg = g_K + (size_t)z * S_ * DK_;
    const float* Vg = g_Vt + (size_t)z * DK_ * S_;
    const int tid = threadIdx.x, lane = tid & 31, w = tid >> 5;
    const int g = lane >> 2, tig = lane & 3;
    const int m0 = w * 16;
    const int qrow0 = blockIdx.x * 128;

    // K cp.async mapping: row = tid>>2 (64 rows), 8 chunks of 16B
    const int krow = tid >> 2, kc0 = (tid & 3) * 32;   // float col base
    uint32_t sK[2];
    sK[0] = smem_u32(&fs[FL_K0 + krow * 132 + kc0]);
    sK[1] = smem_u32(&fs[FL_K1 + krow * 132 + kc0]);
    const float* Kp = Kg + (size_t)krow * DK_ + kc0;
    // V cp.async mapping: row = tid>>1 (128 rows dk), 8 chunks of 16B (64 floats)
    const int vrow = tid >> 1, vc0 = (tid & 1) * 32;
    uint32_t sV = smem_u32(&fs[FL_V + vrow * 68 + vc0]);
    const float* Vp = Vg + (size_t)vrow * S_ + vc0;

    // prologue: K tile 0
    #pragma unroll
    for (int j = 0; j < 8; ++j) CP16(sK[0] + j * 16, Kp + j * 4);
    CP_COMMIT();

    // Q fill (straight copy; already scaled + tf32)
    for (int e = tid * 4; e < 128 * 128; e += 256 * 4) {
        int r = e >> 7, c = e & 127;
        *(float4*)&fs[FL_Q + r * 132 + c] =
            *(const float4*)(Qg + (size_t)(qrow0 + r) * DK_ + c);
    }

    float o[16][4];
    #pragma unroll
    for (int ni = 0; ni < 16; ++ni)
        #pragma unroll
        for (int r = 0; r < 4; ++r) o[ni][r] = 0.f;
    float mr0 = -1e30f, mr1 = -1e30f, l0 = 0.f, l1 = 0.f;

    for (int kt = 0; kt < S_ / 64; ++kt) {
        // issue V(kt), then K(kt+1)
        {
            const float* Vs = Vp + kt * 64;
            #pragma unroll
            for (int j = 0; j < 8; ++j) CP16(sV + j * 16, Vs + j * 4);
            CP_COMMIT();
        }
        if (kt + 1 < S_ / 64) {
            const float* Kn = Kp + (size_t)(kt + 1) * 64 * DK_;
            uint32_t dk = sK[(kt + 1) & 1];
            #pragma unroll
            for (int j = 0; j < 8; ++j) CP16(dk + j * 16, Kn + j * 4);
            CP_COMMIT();
            CP_WAIT(2);          // K(kt) done; V(kt), K(kt+1) may be pending
        } else {
            CP_WAIT(1);
        }
        __syncthreads();

        // ---- S = Q K^T ----
        const float* Kb = &fs[(kt & 1) ? FL_K1 : FL_K0];
        float sacc[8][4];
        #pragma unroll
        for (int ni = 0; ni < 8; ++ni)
            #pragma unroll
            for (int r = 0; r < 4; ++r) sacc[ni][r] = 0.f;

        #pragma unroll
        for (int ks = 0; ks < 16; ++ks) {
            uint32_t aq[4];
            const float* qp = &fs[FL_Q + (m0 + g) * 132 + ks * 8 + tig];
            aq[0] = __float_as_uint(qp[0]);
            aq[1] = __float_as_uint(qp[8 * 132]);
            aq[2] = __float_as_uint(qp[4]);
            aq[3] = __float_as_uint(qp[8 * 132 + 4]);
            #pragma unroll
            for (int ni = 0; ni < 8; ++ni) {
                const float* kp = &Kb[(ni * 8 + g) * 132 + ks * 8 + tig];
                uint32_t bb[2] = { __float_as_uint(kp[0]), __float_as_uint(kp[4]) };
                mma1688(sacc[ni], aq, bb);
            }
        }

        // ---- online softmax ----
        float mt0 = -1e30f, mt1 = -1e30f;
        #pragma unroll
        for (int ni = 0; ni < 8; ++ni) {
            mt0 = fmaxf(mt0, fmaxf(sacc[ni][0], sacc[ni][1]));
            mt1 = fmaxf(mt1, fmaxf(sacc[ni][2], sacc[ni][3]));
        }
        mt0 = fmaxf(mt0, __shfl_xor_sync(0xffffffffu, mt0, 1));
        mt0 = fmaxf(mt0, __shfl_xor_sync(0xffffffffu, mt0, 2));
        mt1 = fmaxf(mt1, __shfl_xor_sync(0xffffffffu, mt1, 1));
        mt1 = fmaxf(mt1, __shfl_xor_sync(0xffffffffu, mt1, 2));

        float mn0 = fmaxf(mr0, mt0), mn1 = fmaxf(mr1, mt1);
        float al0 = __expf(mr0 - mn0), al1 = __expf(mr1 - mn1);
        float ls0 = 0.f, ls1 = 0.f;
        #pragma unroll
        for (int ni = 0; ni < 8; ++ni) {
            sacc[ni][0] = __expf(sacc[ni][0] - mn0);
            sacc[ni][1] = __expf(sacc[ni][1] - mn0);
            sacc[ni][2] = __expf(sacc[ni][2] - mn1);
            sacc[ni][3] = __expf(sacc[ni][3] - mn1);
            ls0 += sacc[ni][0] + sacc[ni][1];
            ls1 += sacc[ni][2] + sacc[ni][3];
        }
        ls0 += __shfl_xor_sync(0xffffffffu, ls0, 1);
        ls0 += __shfl_xor_sync(0xffffffffu, ls0, 2);
        ls1 += __shfl_xor_sync(0xffffffffu, ls1, 1);
        ls1 += __shfl_xor_sync(0xffffffffu, ls1, 2);

        l0 = l0 * al0 + ls0;  mr0 = mn0;
        l1 = l1 * al1 + ls1;  mr1 = mn1;

        #pragma unroll
        for (int ni = 0; ni < 16; ++ni) {
            o[ni][0] *= al0; o[ni][1] *= al0;
            o[ni][2] *= al1; o[ni][3] *= al1;
        }

        // ---- write P (warp-private rows) ----
        #pragma unroll
        for (int ni = 0; ni < 8; ++ni) {
            *(float2*)&fs[FL_P + (m0 + g) * 68 + ni * 8 + 2 * tig] =
                make_float2(tf32f(sacc[ni][0]), tf32f(sacc[ni][1]));
            *(float2*)&fs[FL_P + (m0 + g + 8) * 68 + ni * 8 + 2 * tig] =
                make_float2(tf32f(sacc[ni][2]), tf32f(sacc[ni][3]));
        }

        // wait V(kt)
        if (kt + 1 < S_ / 64) { CP_WAIT(1); } else { CP_WAIT(0); }
        __syncthreads();

        // ---- O += P V ----
        #pragma unroll
        for (int ks = 0; ks < 8; ++ks) {
            uint32_t ap[4];
            const float* pp = &fs[FL_P + (m0 + g) * 68 + ks * 8 + tig];
            ap[0] = __float_as_uint(pp[0]);
            ap[1] = __float_as_uint(pp[8 * 68]);
            ap[2] = __float_as_uint(pp[4]);
            ap[3] = __float_as_uint(pp[8 * 68 + 4]);
            #pragma unroll
            for (int ni = 0; ni < 16; ++ni) {
                const float* vp = &fs[FL_V + (ni * 8 + g) * 68 + ks * 8 + tig];
                uint32_t bb[2] = { __float_as_uint(vp[0]), __float_as_uint(vp[4]) };
                mma1688(o[ni], ap, bb);
            }
        }
        __syncthreads();   // V buffer reused next iteration
    }

    // ---- epilogue: normalize, gate, concat layout (tf32-rounded) ----
    float gate = g_gate[z];
    float inv0 = gate / l0, inv1 = gate / l1;
    int r0 = qrow0 + m0 + g, r1 = r0 + 8;
    float* ob0 = g_cat + ((size_t)b * S_ + r0) * (A_ * DK_) + a * DK_;
    float* ob1 = g_cat + ((size_t)b * S_ + r1) * (A_ * DK_) + a * DK_;
    #pragma unroll
    for (int ni = 0; ni < 16; ++ni) {
        int c = ni * 8 + 2 * tig;
        *(float2*)&ob0[c] = make_float2(tf32f(o[ni][0] * inv0), tf32f(o[ni][1] * inv0));
        *(float2*)&ob1[c] = make_float2(tf32f(o[ni][2] * inv1), tf32f(o[ni][3] * inv1));
    }
}

// ---------------- 5) output projection -----------------------------------------
__global__ void __launch_bounds__(256, 2) outproj_tc(const float* __restrict__ bo,
                                                     float* __restrict__ out) {
    const float* Atile = g_cat + (size_t)blockIdx.x * 128 * (A_ * DK_);
    const float* Bt = g_WoT + (size_t)blockIdx.y * 128 * (A_ * DK_);
    float* C = out + (size_t)blockIdx.x * 128 * D_ + blockIdx.y * 128;
    gemm128_pipe<0>(Atile, A_ * DK_, Bt, A_ * DK_, bo + blockIdx.y * 128,
                    C, D_, A_ * DK_, 1.f);
}

// ---------------- launch --------------------------------------------------------
extern "C" void kernel_launch(void* const* d_in, const int* in_sizes, int n_in,
                              void* d_out, int out_size) {
    const float* x  = (const float*)d_in[0];
    const float* Wq = (const float*)d_in[1];
    const float* bq = (const float*)d_in[2];
    const float* Wk = (const float*)d_in[3];
    const float* bk = (const float*)d_in[4];
    const float* Wv = (const float*)d_in[5];
    const float* bv = (const float*)d_in[6];
    const float* Wr = (const float*)d_in[7];
    const float* br = (const float*)d_in[8];
    const float* Wo = (const float*)d_in[9];
    const float* bo = (const float*)d_in[10];
    float* out = (float*)d_out;

    cudaFuncSetAttribute(flash_tc, cudaFuncAttributeMaxDynamicSharedMemorySize,
                         FL_SMEM_FLOATS * (int)sizeof(float));
    cudaFuncSetAttribute(qkv_tc, cudaFuncAttributeMaxDynamicSharedMemorySize,
                         GEMM_SMEM_BYTES);
    cudaFuncSetAttribute(outproj_tc, cudaFuncAttributeMaxDynamicSharedMemorySize,
                         GEMM_SMEM_BYTES);

    mean_kernel     <<<dim3(D_ / 256, B_), 256>>>(x);
    copy_x_tf32     <<<(B_ * S_ * D_) / (256 * 4), 256>>>(x);
    router_kernel   <<<B_, 128>>>(Wr, br);
    transpose_heads <<<dim3(D_ / 32, DK_ / 32, 3 * H_), dim3(32, 8)>>>(Wq, Wk, Wv);
    transpose_wo    <<<dim3((A_ * DK_) / 32, D_ / 32), dim3(32, 8)>>>(Wo);
    qkv_tc          <<<dim3(S_ / 128, 3, B_ * A_), 256, GEMM_SMEM_BYTES>>>(bq, bk, bv);
    flash_tc        <<<dim3(S_ / 128, B_ * A_), 256,
                       FL_SMEM_FLOATS * (int)sizeof(float)>>>();
    outproj_tc      <<<dim3((B_ * S_) / 128, D_ / 128), 256, GEMM_SMEM_BYTES>>>(bo, out);
}

// round 6
// speedup vs baseline: 2.3137x; 1.1273x over previous
#include <cuda_runtime.h>
#include <math.h>
#include <stdint.h>

#define B_  8
#define S_  1024
#define D_  1024
#define H_  16
#define A_  4
#define DK_ 128

// ---------------- scratch (static device allocations) ------------------------
__device__ float g_xmean[B_ * D_];
__device__ int   g_idx [B_ * A_];
__device__ float g_gate[B_ * A_];
__device__ float g_xt [(size_t)B_ * S_ * D_];            // tf32-rounded x
__device__ float g_Q  [(size_t)B_ * A_ * S_ * DK_];      // pre-scaled, tf32
__device__ float g_K  [(size_t)B_ * A_ * S_ * DK_];      // tf32
__device__ float g_Vt [(size_t)B_ * A_ * DK_ * S_];      // transposed [z][dk][s], tf32
__device__ float g_cat[(size_t)B_ * S_ * A_ * DK_];      // tf32
__device__ float g_WqT[(size_t)H_ * DK_ * D_];           // [h][n][k], tf32
__device__ float g_WkT[(size_t)H_ * DK_ * D_];
__device__ float g_WvT[(size_t)H_ * DK_ * D_];
__device__ float g_WoT[(size_t)D_ * (A_ * DK_)];

// ---------------- helpers -----------------------------------------------------
static __device__ __forceinline__ float tf32f(float x) {
    uint32_t u;
    asm("cvt.rna.tf32.f32 %0, %1;" : "=r"(u) : "f"(x));
    return __uint_as_float(u);
}
static __device__ __forceinline__ void mma1688(float* c, const uint32_t* a,
                                               const uint32_t* b) {
    asm volatile(
        "mma.sync.aligned.m16n8k8.row.col.f32.tf32.tf32.f32 "
        "{%0,%1,%2,%3}, {%4,%5,%6,%7}, {%8,%9}, {%0,%1,%2,%3};"
        : "+f"(c[0]), "+f"(c[1]), "+f"(c[2]), "+f"(c[3])
        : "r"(a[0]), "r"(a[1]), "r"(a[2]), "r"(a[3]), "r"(b[0]), "r"(b[1]));
}
static __device__ __forceinline__ uint32_t smem_u32(const void* p) {
    uint32_t a;
    asm("{ .reg .u64 t; cvta.to.shared.u64 t, %1; cvt.u32.u64 %0, t; }"
        : "=r"(a) : "l"(p));
    return a;
}
#define LDSM4(r0, r1, r2, r3, a) \
    asm volatile("ldmatrix.sync.aligned.m8n8.x4.shared.b16 {%0,%1,%2,%3}, [%4];" \
        : "=r"(r0), "=r"(r1), "=r"(r2), "=r"(r3) : "r"(a))
#define CP16(dst, src) \
    asm volatile("cp.async.cg.shared.global [%0], [%1], 16;" :: "r"(dst), "l"(src))
#define CP_COMMIT() asm volatile("cp.async.commit_group;" ::: "memory")
#define CP_WAIT(n)  asm volatile("cp.async.wait_group %0;" :: "n"(n) : "memory")

// ---------------- 1) mean over sequence + tf32 copy of x ----------------------
__global__ void mean_kernel(const float* __restrict__ x) {
    int b = blockIdx.y;
    int d = blockIdx.x * 256 + threadIdx.x;
    const float* xp = x + (size_t)b * S_ * D_ + d;
    float s = 0.f;
    #pragma unroll 4
    for (int t = 0; t < S_; ++t) s += xp[(size_t)t * D_];
    g_xmean[b * D_ + d] = s * (1.0f / (float)S_);
}
__global__ void copy_x_tf32(const float* __restrict__ x) {
    size_t i = ((size_t)blockIdx.x * 256 + threadIdx.x) * 4;
    float4 v = *(const float4*)(x + i);
    v.x = tf32f(v.x); v.y = tf32f(v.y); v.z = tf32f(v.z); v.w = tf32f(v.w);
    *(float4*)(g_xt + i) = v;
}

// ---------------- 2) router ---------------------------------------------------
__global__ void router_kernel(const float* __restrict__ Wr,
                              const float* __restrict__ br) {
    int b = blockIdx.x;
    __shared__ float red[128][H_];
    int tid = threadIdx.x;
    float acc[H_];
    #pragma unroll
    for (int h = 0; h < H_; ++h) acc[h] = 0.f;
    for (int d = tid; d < D_; d += 128) {
        float xv = g_xmean[b * D_ + d];
        #pragma unroll
        for (int h = 0; h < H_; ++h) acc[h] += xv * Wr[d * H_ + h];
    }
    #pragma unroll
    for (int h = 0; h < H_; ++h) red[tid][h] = acc[h];
    __syncthreads();
    if (tid == 0) {
        float logit[H_];
        for (int h = 0; h < H_; ++h) {
            float s = 0.f;
            for (int t = 0; t < 128; ++t) s += red[t][h];
            logit[h] = s + br[h];
        }
        float mx = logit[0];
        for (int h = 1; h < H_; ++h) mx = fmaxf(mx, logit[h]);
        float dist[H_], sum = 0.f;
        for (int h = 0; h < H_; ++h) { dist[h] = expf(logit[h] - mx); sum += dist[h]; }
        for (int h = 0; h < H_; ++h) dist[h] /= sum;
        bool used[H_];
        for (int h = 0; h < H_; ++h) used[h] = false;
        int idxs[A_]; float vals[A_];
        for (int a = 0; a < A_; ++a) {
            int best = -1; float bv = -1.f;
            for (int h = 0; h < H_; ++h)
                if (!used[h] && dist[h] > bv) { bv = dist[h]; best = h; }
            used[best] = true; idxs[a] = best; vals[a] = bv;
        }
        float denom = (float)(H_ - A_);
        float ev[A_];
        for (int a = 0; a < A_; ++a) { ev[a] = expf(vals[a]); denom += ev[a]; }
        for (int a = 0; a < A_; ++a) {
            g_idx [b * A_ + a] = idxs[a];
            g_gate[b * A_ + a] = ev[a] / denom;
        }
    }
}

// ---------------- weight transposes (emit tf32-rounded) -----------------------
__global__ void transpose_heads(const float* __restrict__ Wq,
                                const float* __restrict__ Wk,
                                const float* __restrict__ Wv) {
    __shared__ float t[32][33];
    int zb = blockIdx.z;
    int mat = zb >> 4, h = zb & 15;
    const float* W = (mat == 0) ? Wq : (mat == 1) ? Wk : Wv;
    float*       O = (mat == 0) ? g_WqT : (mat == 1) ? g_WkT : g_WvT;
    int k0 = blockIdx.x * 32, n0 = blockIdx.y * 32;
    int tx = threadIdx.x, ty = threadIdx.y;
    const float* Wh = W + (size_t)h * D_ * DK_;
    float*       Oh = O + (size_t)h * DK_ * D_;
    #pragma unroll
    for (int i = 0; i < 4; ++i)
        t[ty + 8 * i][tx] = Wh[(size_t)(k0 + ty + 8 * i) * DK_ + n0 + tx];
    __syncthreads();
    #pragma unroll
    for (int i = 0; i < 4; ++i)
        Oh[(size_t)(n0 + ty + 8 * i) * D_ + k0 + tx] = tf32f(t[tx][ty + 8 * i]);
}

__global__ void transpose_wo(const float* __restrict__ Wo) {
    __shared__ float t[32][33];
    int k0 = blockIdx.x * 32, n0 = blockIdx.y * 32;
    int tx = threadIdx.x, ty = threadIdx.y;
    #pragma unroll
    for (int i = 0; i < 4; ++i)
        t[ty + 8 * i][tx] = Wo[(size_t)(k0 + ty + 8 * i) * D_ + n0 + tx];
    __syncthreads();
    #pragma unroll
    for (int i = 0; i < 4; ++i)
        g_WoT[(size_t)(n0 + ty + 8 * i) * (A_ * DK_) + k0 + tx] = tf32f(t[tx][ty + 8 * i]);
}

// ======= cp.async + ldmatrix tf32 GEMM: C[128,128] = A[128,K] @ Bt[128,K]^T ===
#define PITCH 36
#define GEMM_SMEM_BYTES (4 * 128 * PITCH * 4)   // 73728

template<int EPI>
static __device__ __forceinline__ void gemm128_pipe(
    const float* __restrict__ A, int lda,
    const float* __restrict__ Bt, int ldb,
    const float* __restrict__ bias,
    float* __restrict__ C, int ldc, int K, float sc)
{
    extern __shared__ float sh[];
    float* As[2] = { sh,                  sh + 128 * PITCH };
    float* Bs[2] = { sh + 2 * 128 * PITCH, sh + 3 * 128 * PITCH };

    const int tid  = threadIdx.x;
    const int lane = tid & 31;
    const int wid  = tid >> 5;
    const int wm   = wid & 3;
    const int wn   = wid >> 2;
    const int g    = lane >> 2;
    const int tig  = lane & 3;

    const int row  = tid >> 1;
    const int half = (tid & 1) * 16;

    const float* Ap = A  + (size_t)row * lda + half;
    const float* Bp = Bt + (size_t)row * ldb + half;
    uint32_t sA[2], sB[2];
    sA[0] = smem_u32(&As[0][row * PITCH + half]);
    sA[1] = smem_u32(&As[1][row * PITCH + half]);
    sB[0] = smem_u32(&Bs[0][row * PITCH + half]);
    sB[1] = smem_u32(&Bs[1][row * PITCH + half]);

    // ldmatrix lane addresses
    const int arow  = lane & 15;              // fragment row within 16
    const int acolq = (lane >> 4) * 4;        // col 0 or 4
    const int brow  = ((lane >> 4) & 1) * 8 + (lane & 7);
    const int bcol  = ((lane >> 3) & 1) * 4;
    uint32_t aAddr[2][2], bAddr[2][4];
    #pragma unroll
    for (int buf = 0; buf < 2; ++buf) {
        uint32_t ab = smem_u32(As[buf]);
        uint32_t bb = smem_u32(Bs[buf]);
        #pragma unroll
        for (int mi = 0; mi < 2; ++mi)
            aAddr[buf][mi] = ab + ((wm * 32 + mi * 16 + arow) * PITCH + acolq) * 4;
        #pragma unroll
        for (int p = 0; p < 4; ++p)
            bAddr[buf][p] = bb + ((wn * 64 + p * 16 + brow) * PITCH + bcol) * 4;
    }

    const int KIT = K >> 5;

    #pragma unroll
    for (int j = 0; j < 4; ++j) {
        CP16(sA[0] + j * 16, Ap + j * 4);
        CP16(sB[0] + j * 16, Bp + j * 4);
    }
    CP_COMMIT();

    float acc[2][8][4];
    #pragma unroll
    for (int mi = 0; mi < 2; ++mi)
        #pragma unroll
        for (int ni = 0; ni < 8; ++ni)
            #pragma unroll
            for (int r = 0; r < 4; ++r) acc[mi][ni][r] = 0.f;

    for (int it = 0; it < KIT; ++it) {
        if (it + 1 < KIT) {
            const float* An = Ap + (size_t)(it + 1) * 32;
            const float* Bn = Bp + (size_t)(it + 1) * 32;
            int nb = (it + 1) & 1;
            #pragma unroll
            for (int j = 0; j < 4; ++j) {
                CP16(sA[nb] + j * 16, An + j * 4);
                CP16(sB[nb] + j * 16, Bn + j * 4);
            }
            CP_COMMIT();
            CP_WAIT(1);
        } else {
            CP_WAIT(0);
        }
        __syncthreads();

        const int buf = it & 1;
        #pragma unroll
        for (int ks = 0; ks < 4; ++ks) {
            uint32_t a0[4], a1[4];
            LDSM4(a0[0], a0[1], a0[2], a0[3], aAddr[buf][0] + ks * 32);
            LDSM4(a1[0], a1[1], a1[2], a1[3], aAddr[buf][1] + ks * 32);
            #pragma unroll
            for (int p = 0; p < 4; ++p) {
                uint32_t bb[4];
                LDSM4(bb[0], bb[1], bb[2], bb[3], bAddr[buf][p] + ks * 32);
                mma1688(acc[0][2 * p],     a0, bb);
                mma1688(acc[1][2 * p],     a1, bb);
                mma1688(acc[0][2 * p + 1], a0, bb + 2);
                mma1688(acc[1][2 * p + 1], a1, bb + 2);
            }
        }
        __syncthreads();
    }

    #pragma unroll
    for (int mi = 0; mi < 2; ++mi) {
        int r0 = wm * 32 + mi * 16 + g;
        #pragma unroll
        for (int ni = 0; ni < 8; ++ni) {
            int c = wn * 64 + ni * 8 + 2 * tig;
            float b0 = __ldg(bias + c), b1 = __ldg(bias + c + 1);
            float v0 = acc[mi][ni][0] + b0, v1 = acc[mi][ni][1] + b1;
            float v2 = acc[mi][ni][2] + b0, v3 = acc[mi][ni][3] + b1;
            if (EPI == 0) {
                *(float2*)&C[(size_t)r0 * ldc + c]       = make_float2(v0, v1);
                *(float2*)&C[(size_t)(r0 + 8) * ldc + c] = make_float2(v2, v3);
            } else if (EPI == 1) {
                *(float2*)&C[(size_t)r0 * ldc + c] =
                    make_float2(tf32f(v0 * sc), tf32f(v1 * sc));
                *(float2*)&C[(size_t)(r0 + 8) * ldc + c] =
                    make_float2(tf32f(v2 * sc), tf32f(v3 * sc));
            } else if (EPI == 2) {
                C[(size_t)c * ldc + r0]           = tf32f(v0);
                C[(size_t)(c + 1) * ldc + r0]     = tf32f(v1);
                C[(size_t)c * ldc + r0 + 8]       = tf32f(v2);
                C[(size_t)(c + 1) * ldc + r0 + 8] = tf32f(v3);
            } else {
                *(float2*)&C[(size_t)r0 * ldc + c] =
                    make_float2(tf32f(v0), tf32f(v1));
                *(float2*)&C[(size_t)(r0 + 8) * ldc + c] =
                    make_float2(tf32f(v2), tf32f(v3));
            }
        }
    }
}

// ---------------- 3) gathered QKV projections ---------------------------------
__global__ void __launch_bounds__(256, 2) qkv_tc(const float* __restrict__ bq,
                                                 const float* __restrict__ bk,
                                                 const float* __restrict__ bv) {
    int z = blockIdx.z;
    int b = z >> 2;
    int h = g_idx[z];
    const float* Atile = g_xt + (size_t)b * S_ * D_ + (size_t)blockIdx.x * 128 * D_;
    const float sc = 0.08838834764831845f;
    if (blockIdx.y == 0) {
        float* C = g_Q + (size_t)z * S_ * DK_ + (size_t)blockIdx.x * 128 * DK_;
        gemm128_pipe<1>(Atile, D_, g_WqT + (size_t)h * DK_ * D_, D_,
                        bq + h * DK_, C, DK_, D_, sc);
    } else if (blockIdx.y == 1) {
        float* C = g_K + (size_t)z * S_ * DK_ + (size_t)blockIdx.x * 128 * DK_;
        gemm128_pipe<3>(Atile, D_, g_WkT + (size_t)h * DK_ * D_, D_,
                        bk + h * DK_, C, DK_, D_, 1.f);
    } else {
        float* C = g_Vt + (size_t)z * DK_ * S_ + blockIdx.x * 128;
        gemm128_pipe<2>(Atile, D_, g_WvT + (size_t)h * DK_ * D_, D_,
                        bv + h * DK_, C, S_, D_, 1.f);
    }
}

// ---------------- 4) tensor-core flash attention (ldmatrix + cp.async) -------
#define FL_Q   0
#define FL_K0  16896
#define FL_K1  25344
#define FL_V   33792
#define FL_P   42496
#define FL_SMEM_FLOATS 51200

__global__ void __launch_bounds__(256, 1) flash_tc() {
    extern __shared__ float fs[];
    const int z = blockIdx.y, b = z >> 2, a = z & 3;
    const float* Qg = g_Q + (size_t)z * S_ * DK_;
    const float* Kg = g_K + (size_t)z * S_ * DK_;
    const float* Vg = g_Vt + (size_t)z * DK_ * S_;
    const int tid = threadIdx.x, lane = tid & 31, w = tid >> 5;
    const int g = lane >> 2, tig = lane & 3;
    const int m0 = w * 16;
    const int qrow0 = blockIdx.x * 128;

    // cp.async mappings
    const int krow = tid >> 2, kc0 = (tid & 3) * 32;
    uint32_t sK[2];
    sK[0] = smem_u32(&fs[FL_K0 + krow * 132 + kc0]);
    sK[1] = smem_u32(&fs[FL_K1 + krow * 132 + kc0]);
    const float* Kp = Kg + (size_t)krow * DK_ + kc0;
    const int vrow = tid >> 1, vc0 = (tid & 1) * 32;
    uint32_t sV = smem_u32(&fs[FL_V + vrow * 68 + vc0]);
    const float* Vp = Vg + (size_t)vrow * S_ + vc0;

    // ldmatrix lane addresses
    const int arow  = lane & 15;
    const int acolq = (lane >> 4) * 4;
    const int brow  = ((lane >> 4) & 1) * 8 + (lane & 7);
    const int bcol  = ((lane >> 3) & 1) * 4;
    const uint32_t fsb = smem_u32(fs);
    const uint32_t qAddr = fsb + (FL_Q + (m0 + arow) * 132 + acolq) * 4;
    const uint32_t pAddr = fsb + (FL_P + (m0 + arow) * 68 + acolq) * 4;
    uint32_t kAddr[2][4], vAddr[8];
    #pragma unroll
    for (int p = 0; p < 4; ++p) {
        kAddr[0][p] = fsb + (FL_K0 + (p * 16 + brow) * 132 + bcol) * 4;
        kAddr[1][p] = fsb + (FL_K1 + (p * 16 + brow) * 132 + bcol) * 4;
    }
    #pragma unroll
    for (int p = 0; p < 8; ++p)
        vAddr[p] = fsb + (FL_V + (p * 16 + brow) * 68 + bcol) * 4;

    // prologue: K tile 0
    #pragma unroll
    for (int j = 0; j < 8; ++j) CP16(sK[0] + j * 16, Kp + j * 4);
    CP_COMMIT();

    // Q fill (already scaled + tf32)
    for (int e = tid * 4; e < 128 * 128; e += 256 * 4) {
        int r = e >> 7, c = e & 127;
        *(float4*)&fs[FL_Q + r * 132 + c] =
            *(const float4*)(Qg + (size_t)(qrow0 + r) * DK_ + c);
    }

    float o[16][4];
    #pragma unroll
    for (int ni = 0; ni < 16; ++ni)
        #pragma unroll
        for (int r = 0; r < 4; ++r) o[ni][r] = 0.f;
    float mr0 = -1e30f, mr1 = -1e30f, l0 = 0.f, l1 = 0.f;

    for (int kt = 0; kt < S_ / 64; ++kt) {
        {
            const float* Vs = Vp + kt * 64;
            #pragma unroll
            for (int j = 0; j < 8; ++j) CP16(sV + j * 16, Vs + j * 4);
            CP_COMMIT();
        }
        if (kt + 1 < S_ / 64) {
            const float* Kn = Kp + (size_t)(kt + 1) * 64 * DK_;
            uint32_t dk = sK[(kt + 1) & 1];
            #pragma unroll
            for (int j = 0; j < 8; ++j) CP16(dk + j * 16, Kn + j * 4);
            CP_COMMIT();
            CP_WAIT(2);
        } else {
            CP_WAIT(1);
        }
        __syncthreads();

        // ---- S = Q K^T ----
        const int kb = kt & 1;
        float sacc[8][4];
        #pragma unroll
        for (int ni = 0; ni < 8; ++ni)
            #pragma unroll
            for (int r = 0; r < 4; ++r) sacc[ni][r] = 0.f;

        #pragma unroll
        for (int ks = 0; ks < 16; ++ks) {
            uint32_t aq[4];
            LDSM4(aq[0], aq[1], aq[2], aq[3], qAddr + ks * 32);
            #pragma unroll
            for (int p = 0; p < 4; ++p) {
                uint32_t bb[4];
                LDSM4(bb[0], bb[1], bb[2], bb[3], kAddr[kb][p] + ks * 32);
                mma1688(sacc[2 * p],     aq, bb);
                mma1688(sacc[2 * p + 1], aq, bb + 2);
            }
        }

        // ---- online softmax ----
        float mt0 = -1e30f, mt1 = -1e30f;
        #pragma unroll
        for (int ni = 0; ni < 8; ++ni) {
            mt0 = fmaxf(mt0, fmaxf(sacc[ni][0], sacc[ni][1]));
            mt1 = fmaxf(mt1, fmaxf(sacc[ni][2], sacc[ni][3]));
        }
        mt0 = fmaxf(mt0, __shfl_xor_sync(0xffffffffu, mt0, 1));
        mt0 = fmaxf(mt0, __shfl_xor_sync(0xffffffffu, mt0, 2));
        mt1 = fmaxf(mt1, __shfl_xor_sync(0xffffffffu, mt1, 1));
        mt1 = fmaxf(mt1, __shfl_xor_sync(0xffffffffu, mt1, 2));

        float mn0 = fmaxf(mr0, mt0), mn1 = fmaxf(mr1, mt1);
        float al0 = __expf(mr0 - mn0), al1 = __expf(mr1 - mn1);
        float ls0 = 0.f, ls1 = 0.f;
        #pragma unroll
        for (int ni = 0; ni < 8; ++ni) {
            sacc[ni][0] = __expf(sacc[ni][0] - mn0);
            sacc[ni][1] = __expf(sacc[ni][1] - mn0);
            sacc[ni][2] = __expf(sacc[ni][2] - mn1);
            sacc[ni][3] = __expf(sacc[ni][3] - mn1);
            ls0 += sacc[ni][0] + sacc[ni][1];
            ls1 += sacc[ni][2] + sacc[ni][3];
        }
        ls0 += __shfl_xor_sync(0xffffffffu, ls0, 1);
        ls0 += __shfl_xor_sync(0xffffffffu, ls0, 2);
        ls1 += __shfl_xor_sync(0xffffffffu, ls1, 1);
        ls1 += __shfl_xor_sync(0xffffffffu, ls1, 2);

        l0 = l0 * al0 + ls0;  mr0 = mn0;
        l1 = l1 * al1 + ls1;  mr1 = mn1;

        #pragma unroll
        for (int ni = 0; ni < 16; ++ni) {
            o[ni][0] *= al0; o[ni][1] *= al0;
            o[ni][2] *= al1; o[ni][3] *= al1;
        }

        // ---- write P (warp-private rows) ----
        #pragma unroll
        for (int ni = 0; ni < 8; ++ni) {
            *(float2*)&fs[FL_P + (m0 + g) * 68 + ni * 8 + 2 * tig] =
                make_float2(tf32f(sacc[ni][0]), tf32f(sacc[ni][1]));
            *(float2*)&fs[FL_P + (m0 + g + 8) * 68 + ni * 8 + 2 * tig] =
                make_float2(tf32f(sacc[ni][2]), tf32f(sacc[ni][3]));
        }

        if (kt + 1 < S_ / 64) { CP_WAIT(1); } else { CP_WAIT(0); }
        __syncthreads();

        // ---- O += P V ----
        #pragma unroll
        for (int ks = 0; ks < 8; ++ks) {
            uint32_t ap[4];
            LDSM4(ap[0], ap[1], ap[2], ap[3], pAddr + ks * 32);
            #pragma unroll
            for (int p = 0; p < 8; ++p) {
                uint32_t bb[4];
                LDSM4(bb[0], bb[1], bb[2], bb[3], vAddr[p] + ks * 32);
                mma1688(o[2 * p],     ap, bb);
                mma1688(o[2 * p + 1], ap, bb + 2);
            }
        }
        __syncthreads();
    }

    // ---- epilogue: normalize, gate, concat layout (tf32-rounded) ----
    float gate = g_gate[z];
    float inv0 = gate / l0, inv1 = gate / l1;
    int r0 = qrow0 + m0 + g, r1 = r0 + 8;
    float* ob0 = g_cat + ((size_t)b * S_ + r0) * (A_ * DK_) + a * DK_;
    float* ob1 = g_cat + ((size_t)b * S_ + r1) * (A_ * DK_) + a * DK_;
    #pragma unroll
    for (int ni = 0; ni < 16; ++ni) {
        int c = ni * 8 + 2 * tig;
        *(float2*)&ob0[c] = make_float2(tf32f(o[ni][0] * inv0), tf32f(o[ni][1] * inv0));
        *(float2*)&ob1[c] = make_float2(tf32f(o[ni][2] * inv1), tf32f(o[ni][3] * inv1));
    }
}

// ---------------- 5) output projection -----------------------------------------
__global__ void __launch_bounds__(256, 2) outproj_tc(const float* __restrict__ bo,
                                                     float* __restrict__ out) {
    const float* Atile = g_cat + (size_t)blockIdx.x * 128 * (A_ * DK_);
    const float* Bt = g_WoT + (size_t)blockIdx.y * 128 * (A_ * DK_);
    float* C = out + (size_t)blockIdx.x * 128 * D_ + blockIdx.y * 128;
    gemm128_pipe<0>(Atile, A_ * DK_, Bt, A_ * DK_, bo + blockIdx.y * 128,
                    C, D_, A_ * DK_, 1.f);
}

// ---------------- launch --------------------------------------------------------
extern "C" void kernel_launch(void* const* d_in, const int* in_sizes, int n_in,
                              void* d_out, int out_size) {
    const float* x  = (const float*)d_in[0];
    const float* Wq = (const float*)d_in[1];
    const float* bq = (const float*)d_in[2];
    const float* Wk = (const float*)d_in[3];
    const float* bk = (const float*)d_in[4];
    const float* Wv = (const float*)d_in[5];
    const float* bv = (const float*)d_in[6];
    const float* Wr = (const float*)d_in[7];
    const float* br = (const float*)d_in[8];
    const float* Wo = (const float*)d_in[9];
    const float* bo = (const float*)d_in[10];
    float* out = (float*)d_out;

    cudaFuncSetAttribute(flash_tc, cudaFuncAttributeMaxDynamicSharedMemorySize,
                         FL_SMEM_FLOATS * (int)sizeof(float));
    cudaFuncSetAttribute(qkv_tc, cudaFuncAttributeMaxDynamicSharedMemorySize,
                         GEMM_SMEM_BYTES);
    cudaFuncSetAttribute(outproj_tc, cudaFuncAttributeMaxDynamicSharedMemorySize,
                         GEMM_SMEM_BYTES);

    mean_kernel     <<<dim3(D_ / 256, B_), 256>>>(x);
    copy_x_tf32     <<<(B_ * S_ * D_) / (256 * 4), 256>>>(x);
    router_kernel   <<<B_, 128>>>(Wr, br);
    transpose_heads <<<dim3(D_ / 32, DK_ / 32, 3 * H_), dim3(32, 8)>>>(Wq, Wk, Wv);
    transpose_wo    <<<dim3((A_ * DK_) / 32, D_ / 32), dim3(32, 8)>>>(Wo);
    qkv_tc          <<<dim3(S_ / 128, 3, B_ * A_), 256, GEMM_SMEM_BYTES>>>(bq, bk, bv);
    flash_tc        <<<dim3(S_ / 128, B_ * A_), 256,
                       FL_SMEM_FLOATS * (int)sizeof(float)>>>();
    outproj_tc      <<<dim3((B_ * S_) / 128, D_ / 128), 256, GEMM_SMEM_BYTES>>>(bo, out);
}

// round 7
// speedup vs baseline: 3.6755x; 1.5886x over previous
#include <cuda_runtime.h>
#include <cuda_fp16.h>
#include <math.h>
#include <stdint.h>

#define B_  8
#define S_  1024
#define D_  1024
#define H_  16
#define A_  4
#define DK_ 128

// ---------------- scratch (static device allocations) ------------------------
__device__ float g_xmean[B_ * D_];
__device__ int   g_idx [B_ * A_];
__device__ float g_gate[B_ * A_];
__device__ __align__(16) __half g_xh [(size_t)B_ * S_ * D_];        // fp16 x
__device__ __align__(16) __half g_Q  [(size_t)B_ * A_ * S_ * DK_];  // pre-scaled
__device__ __align__(16) __half g_K  [(size_t)B_ * A_ * S_ * DK_];
__device__ __align__(16) __half g_Vt [(size_t)B_ * A_ * DK_ * S_];  // [z][dk][s]
__device__ __align__(16) __half g_cat[(size_t)B_ * S_ * A_ * DK_];
__device__ __align__(16) __half g_WqT[(size_t)H_ * DK_ * D_];       // [h][n][k]
__device__ __align__(16) __half g_WkT[(size_t)H_ * DK_ * D_];
__device__ __align__(16) __half g_WvT[(size_t)H_ * DK_ * D_];
__device__ __align__(16) __half g_WoT[(size_t)D_ * (A_ * DK_)];

// ---------------- helpers -----------------------------------------------------
static __device__ __forceinline__ void mma16816(float* c, const uint32_t* a,
                                                const uint32_t* b) {
    asm volatile(
        "mma.sync.aligned.m16n8k16.row.col.f32.f16.f16.f32 "
        "{%0,%1,%2,%3}, {%4,%5,%6,%7}, {%8,%9}, {%0,%1,%2,%3};"
        : "+f"(c[0]), "+f"(c[1]), "+f"(c[2]), "+f"(c[3])
        : "r"(a[0]), "r"(a[1]), "r"(a[2]), "r"(a[3]), "r"(b[0]), "r"(b[1]));
}
static __device__ __forceinline__ uint32_t smem_u32(const void* p) {
    uint32_t a;
    asm("{ .reg .u64 t; cvta.to.shared.u64 t, %1; cvt.u32.u64 %0, t; }"
        : "=r"(a) : "l"(p));
    return a;
}
#define LDSM4(r0, r1, r2, r3, a) \
    asm volatile("ldmatrix.sync.aligned.m8n8.x4.shared.b16 {%0,%1,%2,%3}, [%4];" \
        : "=r"(r0), "=r"(r1), "=r"(r2), "=r"(r3) : "r"(a))
#define CP16(dst, src) \
    asm volatile("cp.async.cg.shared.global [%0], [%1], 16;" :: "r"(dst), "l"(src))
#define CP_COMMIT() asm volatile("cp.async.commit_group;" ::: "memory")
#define CP_WAIT(n)  asm volatile("cp.async.wait_group %0;" :: "n"(n) : "memory")

// ---------------- 1) mean + fp16 copy of x ------------------------------------
__global__ void mean_kernel(const float* __restrict__ x) {
    int b = blockIdx.y;
    int d = blockIdx.x * 256 + threadIdx.x;
    const float* xp = x + (size_t)b * S_ * D_ + d;
    float s = 0.f;
    #pragma unroll 4
    for (int t = 0; t < S_; ++t) s += xp[(size_t)t * D_];
    g_xmean[b * D_ + d] = s * (1.0f / (float)S_);
}
__global__ void copy_x_h(const float* __restrict__ x) {
    size_t i = ((size_t)blockIdx.x * 256 + threadIdx.x) * 8;
    float4 v0 = *(const float4*)(x + i);
    float4 v1 = *(const float4*)(x + i + 4);
    __half2 h[4] = { __floats2half2_rn(v0.x, v0.y), __floats2half2_rn(v0.z, v0.w),
                     __floats2half2_rn(v1.x, v1.y), __floats2half2_rn(v1.z, v1.w) };
    *(uint4*)(g_xh + i) = *(uint4*)h;
}

// ---------------- 2) router ---------------------------------------------------
__global__ void router_kernel(const float* __restrict__ Wr,
                              const float* __restrict__ br) {
    int b = blockIdx.x;
    __shared__ float red[128][H_];
    int tid = threadIdx.x;
    float acc[H_];
    #pragma unroll
    for (int h = 0; h < H_; ++h) acc[h] = 0.f;
    for (int d = tid; d < D_; d += 128) {
        float xv = g_xmean[b * D_ + d];
        #pragma unroll
        for (int h = 0; h < H_; ++h) acc[h] += xv * Wr[d * H_ + h];
    }
    #pragma unroll
    for (int h = 0; h < H_; ++h) red[tid][h] = acc[h];
    __syncthreads();
    if (tid == 0) {
        float logit[H_];
        for (int h = 0; h < H_; ++h) {
            float s = 0.f;
            for (int t = 0; t < 128; ++t) s += red[t][h];
            logit[h] = s + br[h];
        }
        float mx = logit[0];
        for (int h = 1; h < H_; ++h) mx = fmaxf(mx, logit[h]);
        float dist[H_], sum = 0.f;
        for (int h = 0; h < H_; ++h) { dist[h] = expf(logit[h] - mx); sum += dist[h]; }
        for (int h = 0; h < H_; ++h) dist[h] /= sum;
        bool used[H_];
        for (int h = 0; h < H_; ++h) used[h] = false;
        int idxs[A_]; float vals[A_];
        for (int a = 0; a < A_; ++a) {
            int best = -1; float bv = -1.f;
            for (int h = 0; h < H_; ++h)
                if (!used[h] && dist[h] > bv) { bv = dist[h]; best = h; }
            used[best] = true; idxs[a] = best; vals[a] = bv;
        }
        float denom = (float)(H_ - A_);
        float ev[A_];
        for (int a = 0; a < A_; ++a) { ev[a] = expf(vals[a]); denom += ev[a]; }
        for (int a = 0; a < A_; ++a) {
            g_idx [b * A_ + a] = idxs[a];
            g_gate[b * A_ + a] = ev[a] / denom;
        }
    }
}

// ---------------- weight transposes (emit fp16) -------------------------------
__global__ void transpose_heads(const float* __restrict__ Wq,
                                const float* __restrict__ Wk,
                                const float* __restrict__ Wv) {
    __shared__ float t[32][33];
    int zb = blockIdx.z;
    int mat = zb >> 4, h = zb & 15;
    const float* W = (mat == 0) ? Wq : (mat == 1) ? Wk : Wv;
    __half*      O = (mat == 0) ? g_WqT : (mat == 1) ? g_WkT : g_WvT;
    int k0 = blockIdx.x * 32, n0 = blockIdx.y * 32;
    int tx = threadIdx.x, ty = threadIdx.y;
    const float* Wh = W + (size_t)h * D_ * DK_;
    __half*      Oh = O + (size_t)h * DK_ * D_;
    #pragma unroll
    for (int i = 0; i < 4; ++i)
        t[ty + 8 * i][tx] = Wh[(size_t)(k0 + ty + 8 * i) * DK_ + n0 + tx];
    __syncthreads();
    #pragma unroll
    for (int i = 0; i < 4; ++i)
        Oh[(size_t)(n0 + ty + 8 * i) * D_ + k0 + tx] = __float2half_rn(t[tx][ty + 8 * i]);
}

__global__ void transpose_wo(const float* __restrict__ Wo) {
    __shared__ float t[32][33];
    int k0 = blockIdx.x * 32, n0 = blockIdx.y * 32;
    int tx = threadIdx.x, ty = threadIdx.y;
    #pragma unroll
    for (int i = 0; i < 4; ++i)
        t[ty + 8 * i][tx] = Wo[(size_t)(k0 + ty + 8 * i) * D_ + n0 + tx];
    __syncthreads();
    #pragma unroll
    for (int i = 0; i < 4; ++i)
        g_WoT[(size_t)(n0 + ty + 8 * i) * (A_ * DK_) + k0 + tx] =
            __float2half_rn(t[tx][ty + 8 * i]);
}

// ======= fp16 cp.async + ldmatrix GEMM: C[128,128] = A[128,K] @ Bt[128,K]^T ===
// A, Bt fp16 K-major. K chunk = 64 halves (128B/row). PITCH_H = 72 halves.
#define PITCH_H 72
#define GEMM_SMEM_BYTES (4 * 128 * PITCH_H * 2)   // 73728

// EPI: 0 plain fp32 out (+bias), 1 Q ((acc+bias)*sc -> fp16),
//      2 V transposed (+bias -> fp16), 3 K (+bias -> fp16)
template<int EPI>
static __device__ __forceinline__ void gemm128_h(
    const __half* __restrict__ A, int lda,
    const __half* __restrict__ Bt, int ldb,
    const float* __restrict__ bias,
    void* __restrict__ Cv, int ldc, int K, float sc)
{
    extern __shared__ __half shh[];
    const uint32_t base = smem_u32(shh);
    const uint32_t bufA[2] = { base,                     base + 128 * PITCH_H * 2 };
    const uint32_t bufB[2] = { base + 2 * 128 * PITCH_H * 2, base + 3 * 128 * PITCH_H * 2 };

    const int tid  = threadIdx.x;
    const int lane = tid & 31;
    const int wid  = tid >> 5;
    const int wm   = wid & 3;
    const int wn   = wid >> 2;
    const int g    = lane >> 2;
    const int tig  = lane & 3;

    // cp.async mapping: 128 rows x 128B per matrix; thread -> row=tid>>1, 64B half
    const int row = tid >> 1;
    const int hh  = (tid & 1);
    const __half* Ap = A  + (size_t)row * lda + hh * 32;
    const __half* Bp = Bt + (size_t)row * ldb + hh * 32;
    uint32_t sA[2], sB[2];
    sA[0] = bufA[0] + row * (PITCH_H * 2) + hh * 64;
    sA[1] = bufA[1] + row * (PITCH_H * 2) + hh * 64;
    sB[0] = bufB[0] + row * (PITCH_H * 2) + hh * 64;
    sB[1] = bufB[1] + row * (PITCH_H * 2) + hh * 64;

    // ldmatrix lane addressing
    const int arow = lane & 15;
    const int aco  = (lane >> 4) * 16;           // byte offset
    const int brow = ((lane >> 4) & 1) * 8 + (lane & 7);
    const int bco  = ((lane >> 3) & 1) * 16;
    uint32_t aAddr[2][2], bAddr[2][4];
    #pragma unroll
    for (int buf = 0; buf < 2; ++buf) {
        #pragma unroll
        for (int mi = 0; mi < 2; ++mi)
            aAddr[buf][mi] = bufA[buf] + (wm * 32 + mi * 16 + arow) * (PITCH_H * 2) + aco;
        #pragma unroll
        for (int p = 0; p < 4; ++p)
            bAddr[buf][p] = bufB[buf] + (wn * 64 + p * 16 + brow) * (PITCH_H * 2) + bco;
    }

    const int KIT = K >> 6;

    #pragma unroll
    for (int j = 0; j < 4; ++j) {
        CP16(sA[0] + j * 16, Ap + j * 8);
        CP16(sB[0] + j * 16, Bp + j * 8);
    }
    CP_COMMIT();

    float acc[2][8][4];
    #pragma unroll
    for (int mi = 0; mi < 2; ++mi)
        #pragma unroll
        for (int ni = 0; ni < 8; ++ni)
            #pragma unroll
            for (int r = 0; r < 4; ++r) acc[mi][ni][r] = 0.f;

    for (int it = 0; it < KIT; ++it) {
        if (it + 1 < KIT) {
            const __half* An = Ap + (size_t)(it + 1) * 64;
            const __half* Bn = Bp + (size_t)(it + 1) * 64;
            int nb = (it + 1) & 1;
            #pragma unroll
            for (int j = 0; j < 4; ++j) {
                CP16(sA[nb] + j * 16, An + j * 8);
                CP16(sB[nb] + j * 16, Bn + j * 8);
            }
            CP_COMMIT();
            CP_WAIT(1);
        } else {
            CP_WAIT(0);
        }
        __syncthreads();

        const int buf = it & 1;
        #pragma unroll
        for (int ks = 0; ks < 4; ++ks) {         // 4 x k16
            uint32_t a0[4], a1[4];
            LDSM4(a0[0], a0[1], a0[2], a0[3], aAddr[buf][0] + ks * 32);
            LDSM4(a1[0], a1[1], a1[2], a1[3], aAddr[buf][1] + ks * 32);
            #pragma unroll
            for (int p = 0; p < 4; ++p) {
                uint32_t bb[4];
                LDSM4(bb[0], bb[1], bb[2], bb[3], bAddr[buf][p] + ks * 32);
                mma16816(acc[0][2 * p],     a0, bb);
                mma16816(acc[1][2 * p],     a1, bb);
                mma16816(acc[0][2 * p + 1], a0, bb + 2);
                mma16816(acc[1][2 * p + 1], a1, bb + 2);
            }
        }
        __syncthreads();
    }

    #pragma unroll
    for (int mi = 0; mi < 2; ++mi) {
        int r0 = wm * 32 + mi * 16 + g;
        #pragma unroll
        for (int ni = 0; ni < 8; ++ni) {
            int c = wn * 64 + ni * 8 + 2 * tig;
            float b0 = __ldg(bias + c), b1 = __ldg(bias + c + 1);
            float v0 = acc[mi][ni][0] + b0, v1 = acc[mi][ni][1] + b1;
            float v2 = acc[mi][ni][2] + b0, v3 = acc[mi][ni][3] + b1;
            if (EPI == 0) {
                float* C = (float*)Cv;
                *(float2*)&C[(size_t)r0 * ldc + c]       = make_float2(v0, v1);
                *(float2*)&C[(size_t)(r0 + 8) * ldc + c] = make_float2(v2, v3);
            } else if (EPI == 1) {
                __half* C = (__half*)Cv;
                *(__half2*)&C[(size_t)r0 * ldc + c]       = __floats2half2_rn(v0 * sc, v1 * sc);
                *(__half2*)&C[(size_t)(r0 + 8) * ldc + c] = __floats2half2_rn(v2 * sc, v3 * sc);
            } else if (EPI == 2) {
                __half* C = (__half*)Cv;
                C[(size_t)c * ldc + r0]           = __float2half_rn(v0);
                C[(size_t)(c + 1) * ldc + r0]     = __float2half_rn(v1);
                C[(size_t)c * ldc + r0 + 8]       = __float2half_rn(v2);
                C[(size_t)(c + 1) * ldc + r0 + 8] = __float2half_rn(v3);
            } else {
                __half* C = (__half*)Cv;
                *(__half2*)&C[(size_t)r0 * ldc + c]       = __floats2half2_rn(v0, v1);
                *(__half2*)&C[(size_t)(r0 + 8) * ldc + c] = __floats2half2_rn(v2, v3);
            }
        }
    }
}

// ---------------- 3) gathered QKV projections ---------------------------------
__global__ void __launch_bounds__(256, 2) qkv_tc(const float* __restrict__ bq,
                                                 const float* __restrict__ bk,
                                                 const float* __restrict__ bv) {
    int z = blockIdx.z;
    int b = z >> 2;
    int h = g_idx[z];
    const __half* Atile = g_xh + (size_t)b * S_ * D_ + (size_t)blockIdx.x * 128 * D_;
    const float sc = 0.08838834764831845f;
    if (blockIdx.y == 0) {
        __half* C = g_Q + (size_t)z * S_ * DK_ + (size_t)blockIdx.x * 128 * DK_;
        gemm128_h<1>(Atile, D_, g_WqT + (size_t)h * DK_ * D_, D_,
                     bq + h * DK_, C, DK_, D_, sc);
    } else if (blockIdx.y == 1) {
        __half* C = g_K + (size_t)z * S_ * DK_ + (size_t)blockIdx.x * 128 * DK_;
        gemm128_h<3>(Atile, D_, g_WkT + (size_t)h * DK_ * D_, D_,
                     bk + h * DK_, C, DK_, D_, 1.f);
    } else {
        __half* C = g_Vt + (size_t)z * DK_ * S_ + blockIdx.x * 128;
        gemm128_h<2>(Atile, D_, g_WvT + (size_t)h * DK_ * D_, D_,
                     bv + h * DK_, C, S_, D_, 1.f);
    }
}

// ---------------- 4) fp16 tensor-core flash attention -------------------------
// smem halves: Q[128*136]@0, K0[64*136]@17408, K1@26112, V[128*72]@34816, P@44032
#define FL_Q   0
#define FL_K0  17408
#define FL_K1  26112
#define FL_V   34816
#define FL_P   44032
#define FL_SMEM_BYTES ((44032 + 128 * 72) * 2)   // 106496

__global__ void __launch_bounds__(256, 1) flash_tc() {
    extern __shared__ __half fsh[];
    const int z = blockIdx.y, b = z >> 2, a = z & 3;
    const __half* Qg = g_Q + (size_t)z * S_ * DK_;
    const __half* Kg = g_K + (size_t)z * S_ * DK_;
    const __half* Vg = g_Vt + (size_t)z * DK_ * S_;
    const int tid = threadIdx.x, lane = tid & 31, w = tid >> 5;
    const int g = lane >> 2, tig = lane & 3;
    const int m0 = w * 16;
    const int qrow0 = blockIdx.x * 128;
    const uint32_t fsb = smem_u32(fsh);

    // cp.async mappings
    const int krow = tid >> 2;                  // 64 rows, 256B each
    uint32_t sK[2];
    sK[0] = fsb + (FL_K0 + krow * 136) * 2 + (tid & 3) * 64;
    sK[1] = fsb + (FL_K1 + krow * 136) * 2 + (tid & 3) * 64;
    const __half* Kp = Kg + (size_t)krow * DK_ + (tid & 3) * 32;
    const int vrow = tid >> 1;                  // 128 rows, 128B each
    uint32_t sV = fsb + (FL_V + vrow * 72) * 2 + (tid & 1) * 64;
    const __half* Vp = Vg + (size_t)vrow * S_ + (tid & 1) * 32;

    // ldmatrix lane addressing
    const int arow = lane & 15;
    const int aco  = (lane >> 4) * 16;
    const int brow = ((lane >> 4) & 1) * 8 + (lane & 7);
    const int bco  = ((lane >> 3) & 1) * 16;
    const uint32_t qAddr = fsb + (FL_Q + (m0 + arow) * 136) * 2 + aco;
    const uint32_t pAddr = fsb + (FL_P + (m0 + arow) * 72) * 2 + aco;
    uint32_t kAddr[2][4], vAddr[8];
    #pragma unroll
    for (int p = 0; p < 4; ++p) {
        kAddr[0][p] = fsb + (FL_K0 + (p * 16 + brow) * 136) * 2 + bco;
        kAddr[1][p] = fsb + (FL_K1 + (p * 16 + brow) * 136) * 2 + bco;
    }
    #pragma unroll
    for (int p = 0; p < 8; ++p)
        vAddr[p] = fsb + (FL_V + (p * 16 + brow) * 72) * 2 + bco;

    // prologue: K tile 0
    #pragma unroll
    for (int j = 0; j < 4; ++j) CP16(sK[0] + j * 16, Kp + j * 8);
    CP_COMMIT();

    // Q fill (pre-scaled fp16): 2048 16B-chunks / 256 thr = 8 each
    #pragma unroll
    for (int l = 0; l < 8; ++l) {
        int chunk = tid + l * 256;
        int r = chunk >> 4, c = (chunk & 15) * 8;
        *(uint4*)&fsh[FL_Q + r * 136 + c] =
            *(const uint4*)(Qg + (size_t)(qrow0 + r) * DK_ + c);
    }

    float o[16][4];
    #pragma unroll
    for (int ni = 0; ni < 16; ++ni)
        #pragma unroll
        for (int r = 0; r < 4; ++r) o[ni][r] = 0.f;
    float mr0 = -1e30f, mr1 = -1e30f, l0 = 0.f, l1 = 0.f;

    for (int kt = 0; kt < S_ / 64; ++kt) {
        {
            const __half* Vs = Vp + kt * 64;
            #pragma unroll
            for (int j = 0; j < 4; ++j) CP16(sV + j * 16, Vs + j * 8);
            CP_COMMIT();
        }
        if (kt + 1 < S_ / 64) {
            const __half* Kn = Kp + (size_t)(kt + 1) * 64 * DK_;
            uint32_t dk = sK[(kt + 1) & 1];
            #pragma unroll
            for (int j = 0; j < 4; ++j) CP16(dk + j * 16, Kn + j * 8);
            CP_COMMIT();
            CP_WAIT(2);
        } else {
            CP_WAIT(1);
        }
        __syncthreads();

        // ---- S = Q K^T : 8 k16-steps over dk=128, 4 n16-slabs over 64 keys ----
        const int kb = kt & 1;
        float sacc[8][4];
        #pragma unroll
        for (int ni = 0; ni < 8; ++ni)
            #pragma unroll
            for (int r = 0; r < 4; ++r) sacc[ni][r] = 0.f;

        #pragma unroll
        for (int ks = 0; ks < 8; ++ks) {
            uint32_t aq[4];
            LDSM4(aq[0], aq[1], aq[2], aq[3], qAddr + ks * 32);
            #pragma unroll
            for (int p = 0; p < 4; ++p) {
                uint32_t bb[4];
                LDSM4(bb[0], bb[1], bb[2], bb[3], kAddr[kb][p] + ks * 32);
                mma16816(sacc[2 * p],     aq, bb);
                mma16816(sacc[2 * p + 1], aq, bb + 2);
            }
        }

        // ---- online softmax ----
        float mt0 = -1e30f, mt1 = -1e30f;
        #pragma unroll
        for (int ni = 0; ni < 8; ++ni) {
            mt0 = fmaxf(mt0, fmaxf(sacc[ni][0], sacc[ni][1]));
            mt1 = fmaxf(mt1, fmaxf(sacc[ni][2], sacc[ni][3]));
        }
        mt0 = fmaxf(mt0, __shfl_xor_sync(0xffffffffu, mt0, 1));
        mt0 = fmaxf(mt0, __shfl_xor_sync(0xffffffffu, mt0, 2));
        mt1 = fmaxf(mt1, __shfl_xor_sync(0xffffffffu, mt1, 1));
        mt1 = fmaxf(mt1, __shfl_xor_sync(0xffffffffu, mt1, 2));

        float mn0 = fmaxf(mr0, mt0), mn1 = fmaxf(mr1, mt1);
        float al0 = __expf(mr0 - mn0), al1 = __expf(mr1 - mn1);
        float ls0 = 0.f, ls1 = 0.f;
        #pragma unroll
        for (int ni = 0; ni < 8; ++ni) {
            sacc[ni][0] = __expf(sacc[ni][0] - mn0);
            sacc[ni][1] = __expf(sacc[ni][1] - mn0);
            sacc[ni][2] = __expf(sacc[ni][2] - mn1);
            sacc[ni][3] = __expf(sacc[ni][3] - mn1);
            ls0 += sacc[ni][0] + sacc[ni][1];
            ls1 += sacc[ni][2] + sacc[ni][3];
        }
        ls0 += __shfl_xor_sync(0xffffffffu, ls0, 1);
        ls0 += __shfl_xor_sync(0xffffffffu, ls0, 2);
        ls1 += __shfl_xor_sync(0xffffffffu, ls1, 1);
        ls1 += __shfl_xor_sync(0xffffffffu, ls1, 2);

        l0 = l0 * al0 + ls0;  mr0 = mn0;
        l1 = l1 * al1 + ls1;  mr1 = mn1;

        #pragma unroll
        for (int ni = 0; ni < 16; ++ni) {
            o[ni][0] *= al0; o[ni][1] *= al0;
            o[ni][2] *= al1; o[ni][3] *= al1;
        }

        // ---- write P (warp-private rows, fp16) ----
        #pragma unroll
        for (int ni = 0; ni < 8; ++ni) {
            *(__half2*)&fsh[FL_P + (m0 + g) * 72 + ni * 8 + 2 * tig] =
                __floats2half2_rn(sacc[ni][0], sacc[ni][1]);
            *(__half2*)&fsh[FL_P + (m0 + g + 8) * 72 + ni * 8 + 2 * tig] =
                __floats2half2_rn(sacc[ni][2], sacc[ni][3]);
        }

        if (kt + 1 < S_ / 64) { CP_WAIT(1); } else { CP_WAIT(0); }
        __syncthreads();

        // ---- O += P V : 4 k16-steps over 64 keys, 8 n16-slabs over dk ----
        #pragma unroll
        for (int ks = 0; ks < 4; ++ks) {
            uint32_t ap[4];
            LDSM4(ap[0], ap[1], ap[2], ap[3], pAddr + ks * 32);
            #pragma unroll
            for (int p = 0; p < 8; ++p) {
                uint32_t bb[4];
                LDSM4(bb[0], bb[1], bb[2], bb[3], vAddr[p] + ks * 32);
                mma16816(o[2 * p],     ap, bb);
                mma16816(o[2 * p + 1], ap, bb + 2);
            }
        }
        __syncthreads();
    }

    // ---- epilogue: normalize, gate, concat (fp16) ----
    float gate = g_gate[z];
    float inv0 = gate / l0, inv1 = gate / l1;
    int r0 = qrow0 + m0 + g, r1 = r0 + 8;
    __half* ob0 = g_cat + ((size_t)b * S_ + r0) * (A_ * DK_) + a * DK_;
    __half* ob1 = g_cat + ((size_t)b * S_ + r1) * (A_ * DK_) + a * DK_;
    #pragma unroll
    for (int ni = 0; ni < 16; ++ni) {
        int c = ni * 8 + 2 * tig;
        *(__half2*)&ob0[c] = __floats2half2_rn(o[ni][0] * inv0, o[ni][1] * inv0);
        *(__half2*)&ob1[c] = __floats2half2_rn(o[ni][2] * inv1, o[ni][3] * inv1);
    }
}

// ---------------- 5) output projection -----------------------------------------
__global__ void __launch_bounds__(256, 2) outproj_tc(const float* __restrict__ bo,
                                                     float* __restrict__ out) {
    const __half* Atile = g_cat + (size_t)blockIdx.x * 128 * (A_ * DK_);
    const __half* Bt = g_WoT + (size_t)blockIdx.y * 128 * (A_ * DK_);
    float* C = out + (size_t)blockIdx.x * 128 * D_ + blockIdx.y * 128;
    gemm128_h<0>(Atile, A_ * DK_, Bt, A_ * DK_, bo + blockIdx.y * 128,
                 C, D_, A_ * DK_, 1.f);
}

// ---------------- launch --------------------------------------------------------
extern "C" void kernel_launch(void* const* d_in, const int* in_sizes, int n_in,
                              void* d_out, int out_size) {
    const float* x  = (const float*)d_in[0];
    const float* Wq = (const float*)d_in[1];
    const float* bq = (const float*)d_in[2];
    const float* Wk = (const float*)d_in[3];
    const float* bk = (const float*)d_in[4];
    const float* Wv = (const float*)d_in[5];
    const float* bv = (const float*)d_in[6];
    const float* Wr = (const float*)d_in[7];
    const float* br = (const float*)d_in[8];
    const float* Wo = (const float*)d_in[9];
    const float* bo = (const float*)d_in[10];
    float* out = (float*)d_out;

    cudaFuncSetAttribute(flash_tc, cudaFuncAttributeMaxDynamicSharedMemorySize,
                         FL_SMEM_BYTES);
    cudaFuncSetAttribute(qkv_tc, cudaFuncAttributeMaxDynamicSharedMemorySize,
                         GEMM_SMEM_BYTES);
    cudaFuncSetAttribute(outproj_tc, cudaFuncAttributeMaxDynamicSharedMemorySize,
                         GEMM_SMEM_BYTES);

    mean_kernel     <<<dim3(D_ / 256, B_), 256>>>(x);
    copy_x_h        <<<(B_ * S_ * D_) / (256 * 8), 256>>>(x);
    router_kernel   <<<B_, 128>>>(Wr, br);
    transpose_heads <<<dim3(D_ / 32, DK_ / 32, 3 * H_), dim3(32, 8)>>>(Wq, Wk, Wv);
    transpose_wo    <<<dim3((A_ * DK_) / 32, D_ / 32), dim3(32, 8)>>>(Wo);
    qkv_tc          <<<dim3(S_ / 128, 3, B_ * A_), 256, GEMM_SMEM_BYTES>>>(bq, bk, bv);
    flash_tc        <<<dim3(S_ / 128, B_ * A_), 256, FL_SMEM_BYTES>>>();
    outproj_tc      <<<dim3((B_ * S_) / 128, D_ / 128), 256, GEMM_SMEM_BYTES>>>(bo, out);
}